// round 2
// baseline (speedup 1.0000x reference)
#include <cuda_runtime.h>
#include <math.h>

#define BATCH  64
#define TSEQ   3136
#define NTOK   (BATCH*TSEQ)   // 200704
#define INDIM  147
#define DIM    64
#define MF     32

// -------- scratch (__device__ globals: allocation-free rule) --------
__device__ float d_v [NTOK*DIM];     // 51 MB
__device__ float d_kp[NTOK*MF];      // 25.7 MB
__device__ float d_qp[NTOK*MF];      // 25.7 MB
__device__ float d_kpsum[BATCH*MF];
__device__ float d_kptv [BATCH*DIM*MF];

__device__ __forceinline__ float wsum(float v) {
#pragma unroll
    for (int o = 16; o; o >>= 1) v += __shfl_xor_sync(0xffffffffu, v, o);
    return v;
}

// ===================== Kernel A: x -> (v, kp, qp) =====================
// one warp per token; weights in dynamic smem
#define A_THREADS 256
#define A_WARPS   8
#define A_W1   0                       // 147*64 = 9408
#define A_WK   9408                    // 64*192 = 12288
#define A_WT   (9408+12288)            // wT[d][m] 64*32 = 2048
#define A_SX   (A_WT+2048)             // 8 * 148
#define A_SROW (A_SX + A_WARPS*148)    // 8 * 64
#define A_SMEM_FLOATS (A_SROW + A_WARPS*64)
#define A_SMEM_BYTES  (A_SMEM_FLOATS*4)   // 101760 B

__global__ void __launch_bounds__(A_THREADS) kernelA(
    const float* __restrict__ x,  const float* __restrict__ W1, const float* __restrict__ b1,
    const float* __restrict__ Wk, const float* __restrict__ bk,
    const float* __restrict__ g1, const float* __restrict__ be1,
    const float* __restrict__ wrf)
{
    extern __shared__ float sm[];
    const int tid = threadIdx.x, lane = tid & 31, warp = tid >> 5;

    for (int i = tid; i < INDIM*DIM; i += A_THREADS) sm[A_W1 + i] = W1[i];
    for (int i = tid; i < DIM*192;   i += A_THREADS) sm[A_WK + i] = Wk[i];
    for (int i = tid; i < MF*DIM;    i += A_THREADS) {       // transpose w -> [d][m]
        int m = i >> 6, d = i & 63;
        sm[A_WT + d*MF + m] = wrf[i];
    }
    __syncthreads();

    float* sx   = sm + A_SX   + warp*148;
    float* srow = sm + A_SROW + warp*64;
    const float inv64 = 1.0f/64.0f;
    const float rsM   = 0.17677669529663689f;   // 1/sqrt(32)

    for (int token = blockIdx.x*A_WARPS + warp; token < NTOK; token += gridDim.x*A_WARPS) {
        const float* xr = x + (long long)token * INDIM;
        for (int i = lane; i < INDIM; i += 32) sx[i] = xr[i];
        __syncwarp();

        // h = x @ W_proj1 + b ; each lane owns cols lane, lane+32
        float h0 = b1[lane], h1 = b1[lane+32];
#pragma unroll 7
        for (int i = 0; i < INDIM; i++) {
            float xv = sx[i];
            h0 = fmaf(xv, sm[A_W1 + i*64 + lane],      h0);
            h1 = fmaf(xv, sm[A_W1 + i*64 + lane + 32], h1);
        }
        // LN1
        float mu  = wsum(h0 + h1) * inv64;
        float dd0 = h0 - mu, dd1 = h1 - mu;
        float var = wsum(dd0*dd0 + dd1*dd1) * inv64;
        float inv = rsqrtf(var + 1e-5f);
        float hn0 = dd0*inv*g1[lane]    + be1[lane];
        float hn1 = dd1*inv*g1[lane+32] + be1[lane+32];
        __syncwarp();
        srow[lane] = hn0; srow[lane+32] = hn1;
        __syncwarp();

        // kqv: 6 columns per lane  (k: 0..63, q: 64..127, v: 128..191)
        float k0=bk[lane],     k1=bk[lane+32];
        float q0=bk[64+lane],  q1=bk[96+lane];
        float v0=bk[128+lane], v1=bk[160+lane];
#pragma unroll 8
        for (int i = 0; i < DIM; i++) {
            float hv = srow[i];
            const float* wr = sm + A_WK + i*192;
            k0 = fmaf(hv, wr[lane],       k0);
            k1 = fmaf(hv, wr[lane + 32],  k1);
            q0 = fmaf(hv, wr[lane + 64],  q0);
            q1 = fmaf(hv, wr[lane + 96],  q1);
            v0 = fmaf(hv, wr[lane + 128], v0);
            v1 = fmaf(hv, wr[lane + 160], v1);
        }

        // kp = exp(w.k - |k|^2/2)/sqrt(M)
        float xdk = 0.5f * wsum(k0*k0 + k1*k1);
        __syncwarp();
        srow[lane] = k0; srow[lane+32] = k1;
        __syncwarp();
        float wk = 0.f;
#pragma unroll 8
        for (int i = 0; i < DIM; i++) wk = fmaf(sm[A_WT + i*MF + lane], srow[i], wk);
        d_kp[(long long)token*MF + lane] = expf(wk - xdk) * rsM;

        float xdq = 0.5f * wsum(q0*q0 + q1*q1);
        __syncwarp();
        srow[lane] = q0; srow[lane+32] = q1;
        __syncwarp();
        float wq = 0.f;
#pragma unroll 8
        for (int i = 0; i < DIM; i++) wq = fmaf(sm[A_WT + i*MF + lane], srow[i], wq);
        d_qp[(long long)token*MF + lane] = expf(wq - xdq) * rsM;

        d_v[(long long)token*64 + lane]      = v0;
        d_v[(long long)token*64 + lane + 32] = v1;
        __syncwarp();
    }
}

// ===================== zero kpsum / kptv =====================
__global__ void kernelZero() {
    int i = blockIdx.x*blockDim.x + threadIdx.x;
    if (i < BATCH*MF)      d_kpsum[i] = 0.f;
    if (i < BATCH*DIM*MF)  d_kptv[i]  = 0.f;
}

// ===================== Kernel B: kpsum, kptv =====================
// grid (8, 64): T split 8 ways, one batch per blockIdx.y
#define B_TILE 16
__global__ void __launch_bounds__(256) kernelB()
{
    __shared__ float sv [B_TILE*64];
    __shared__ float skp[B_TILE*32];
    const int tid = threadIdx.x;
    const int b   = blockIdx.y;
    const int m   = tid & 31, dg = tid >> 5;     // dg in 0..7 -> d = dg*8+j

    float acc[8];
#pragma unroll
    for (int j = 0; j < 8; j++) acc[j] = 0.f;
    float ks = 0.f;

    const int t0 = blockIdx.x * (TSEQ/8);
    const int t1 = t0 + (TSEQ/8);
    for (int base = t0; base < t1; base += B_TILE) {
        int nt = min(B_TILE, t1 - base);
        __syncthreads();
        for (int idx = tid; idx < B_TILE*64; idx += 256) {
            int r = idx >> 6;
            if (r < nt) sv[idx] = d_v[((long long)(b*TSEQ + base + r))*64 + (idx & 63)];
        }
        for (int idx = tid; idx < B_TILE*32; idx += 256) {
            int r = idx >> 5;
            if (r < nt) skp[idx] = d_kp[((long long)(b*TSEQ + base + r))*32 + (idx & 31)];
        }
        __syncthreads();
        for (int tt = 0; tt < nt; tt++) {
            float kpm = skp[tt*32 + m];
#pragma unroll
            for (int j = 0; j < 8; j++)
                acc[j] = fmaf(kpm, sv[tt*64 + dg*8 + j], acc[j]);
            if (dg == 0) ks += kpm;
        }
    }
#pragma unroll
    for (int j = 0; j < 8; j++)
        atomicAdd(&d_kptv[b*2048 + (dg*8 + j)*32 + m], acc[j]);
    if (dg == 0) atomicAdd(&d_kpsum[b*32 + m], ks);
}

// ===================== Kernel C: attention epilogue + MLP =====================
#define C_W2    0          // 4096
#define C_WM1   4096       // 4096
#define C_WM2   8192       // 4096
#define C_KPTV  12288      // transposed [m][d] 2048
#define C_KPS   14336      // 32
#define C_SROW  14368      // 8*64
#define C_SQP   (C_SROW + 8*64)   // 8*32
#define C_SMEM_FLOATS (C_SQP + 8*32)
#define C_SMEM_BYTES  (C_SMEM_FLOATS*4)   // 60544 B

__global__ void __launch_bounds__(256) kernelC(
    const float* __restrict__ W2,  const float* __restrict__ b2,
    const float* __restrict__ g2,  const float* __restrict__ be2,
    const float* __restrict__ Wm1, const float* __restrict__ bm1,
    const float* __restrict__ Wm2, const float* __restrict__ bm2,
    float* __restrict__ out)
{
    extern __shared__ float sm[];
    const int tid = threadIdx.x, lane = tid & 31, warp = tid >> 5;
    const int b = blockIdx.y;

    for (int i = tid; i < 4096; i += 256) {
        sm[C_W2  + i] = W2[i];
        sm[C_WM1 + i] = Wm1[i];
        sm[C_WM2 + i] = Wm2[i];
    }
    for (int i = tid; i < 2048; i += 256) {      // kptv[b][d][m] -> [m][d]
        int d = i >> 5, m = i & 31;
        sm[C_KPTV + m*64 + d] = d_kptv[b*2048 + i];
    }
    if (tid < 32) sm[C_KPS + tid] = d_kpsum[b*32 + tid];
    __syncthreads();

    float* srow = sm + C_SROW + warp*64;
    float* sqp  = sm + C_SQP  + warp*32;
    const float inv64 = 1.0f/64.0f;

    for (int lt = blockIdx.x*8 + warp; lt < TSEQ; lt += gridDim.x*8) {
        const long long token = (long long)b*TSEQ + lt;

        float qpv = d_qp[token*32 + lane];
        float D   = wsum(qpv * sm[C_KPS + lane]);
        float rD  = 1.0f / (D + 1e-8f);
        sqp[lane] = qpv;
        __syncwarp();

        float a0 = 0.f, a1 = 0.f;
#pragma unroll 8
        for (int mm = 0; mm < 32; mm++) {
            float qv = sqp[mm];
            a0 = fmaf(qv, sm[C_KPTV + mm*64 + lane],      a0);
            a1 = fmaf(qv, sm[C_KPTV + mm*64 + lane + 32], a1);
        }
        a0 *= rD; a1 *= rD;
        __syncwarp();
        srow[lane] = a0; srow[lane+32] = a1;
        __syncwarp();

        // y = v + att @ W_proj2 + b2
        float y0 = d_v[token*64 + lane]      + b2[lane];
        float y1 = d_v[token*64 + lane + 32] + b2[lane+32];
#pragma unroll 8
        for (int i = 0; i < 64; i++) {
            float av = srow[i];
            y0 = fmaf(av, sm[C_W2 + i*64 + lane],      y0);
            y1 = fmaf(av, sm[C_W2 + i*64 + lane + 32], y1);
        }

        // LN2
        float mu  = wsum(y0 + y1) * inv64;
        float dd0 = y0 - mu, dd1 = y1 - mu;
        float var = wsum(dd0*dd0 + dd1*dd1) * inv64;
        float inv = rsqrtf(var + 1e-5f);
        float yn0 = dd0*inv*g2[lane]    + be2[lane];
        float yn1 = dd1*inv*g2[lane+32] + be2[lane+32];
        __syncwarp();
        srow[lane] = yn0; srow[lane+32] = yn1;
        __syncwarp();

        // MLP hidden + exact GELU
        float z0 = bm1[lane], z1 = bm1[lane+32];
#pragma unroll 8
        for (int i = 0; i < 64; i++) {
            float yv = srow[i];
            z0 = fmaf(yv, sm[C_WM1 + i*64 + lane],      z0);
            z1 = fmaf(yv, sm[C_WM1 + i*64 + lane + 32], z1);
        }
        float ge0 = 0.5f*z0*(1.0f + erff(z0*0.70710678118654752f));
        float ge1 = 0.5f*z1*(1.0f + erff(z1*0.70710678118654752f));
        __syncwarp();
        srow[lane] = ge0; srow[lane+32] = ge1;
        __syncwarp();

        float o0 = bm2[lane], o1 = bm2[lane+32];
#pragma unroll 8
        for (int i = 0; i < 64; i++) {
            float gv = srow[i];
            o0 = fmaf(gv, sm[C_WM2 + i*64 + lane],      o0);
            o1 = fmaf(gv, sm[C_WM2 + i*64 + lane + 32], o1);
        }
        out[token*64 + lane]      = y0 + o0;
        out[token*64 + lane + 32] = y1 + o1;
        __syncwarp();
    }
}

// ===================== launch =====================
extern "C" void kernel_launch(void* const* d_in, const int* in_sizes, int n_in,
                              void* d_out, int out_size)
{
    const float* x   = (const float*)d_in[0];
    const float* W1  = (const float*)d_in[1];
    const float* b1  = (const float*)d_in[2];
    const float* Wk  = (const float*)d_in[3];
    const float* bk  = (const float*)d_in[4];
    const float* W2  = (const float*)d_in[5];
    const float* b2  = (const float*)d_in[6];
    const float* g1  = (const float*)d_in[7];
    const float* be1 = (const float*)d_in[8];
    const float* g2  = (const float*)d_in[9];
    const float* be2 = (const float*)d_in[10];
    const float* Wm1 = (const float*)d_in[11];
    const float* bm1 = (const float*)d_in[12];
    const float* Wm2 = (const float*)d_in[13];
    const float* bm2 = (const float*)d_in[14];
    const float* wrf = (const float*)d_in[15];
    float* out = (float*)d_out;

    cudaFuncSetAttribute(kernelA, cudaFuncAttributeMaxDynamicSharedMemorySize, A_SMEM_BYTES);
    cudaFuncSetAttribute(kernelC, cudaFuncAttributeMaxDynamicSharedMemorySize, C_SMEM_BYTES);

    kernelA<<<296, A_THREADS, A_SMEM_BYTES>>>(x, W1, b1, Wk, bk, g1, be1, wrf);
    kernelZero<<<(BATCH*DIM*MF + 255)/256, 256>>>();
    kernelB<<<dim3(8, BATCH), 256>>>();
    kernelC<<<dim3(8, BATCH), 256, C_SMEM_BYTES>>>(W2, b2, g2, be2, Wm1, bm1, Wm2, bm2, out);
}

// round 3
// speedup vs baseline: 1.5139x; 1.5139x over previous
#include <cuda_runtime.h>
#include <math.h>

#define BATCH  64
#define TSEQ   3136
#define NTOK   (BATCH*TSEQ)   // 200704
#define INDIM  147
#define DIM    64
#define MF     32
#define TB     4              // tokens per warp
#define NW     16             // warps per block (512 threads)

// -------- scratch --------
__device__ float d_v [NTOK*DIM];
__device__ float d_kp[NTOK*MF];
__device__ float d_qp[NTOK*MF];
__device__ float d_kpsum[BATCH*MF];
__device__ float d_kptv [BATCH*DIM*MF];

__device__ __forceinline__ float wsum(float v) {
#pragma unroll
    for (int o = 16; o; o >>= 1) v += __shfl_xor_sync(0xffffffffu, v, o);
    return v;
}
__device__ __forceinline__ float dot4(float4 a, float4 b, float acc) {
    acc = fmaf(a.x, b.x, acc); acc = fmaf(a.y, b.y, acc);
    acc = fmaf(a.z, b.z, acc); acc = fmaf(a.w, b.w, acc);
    return acc;
}

// ===================== Kernel A =====================
// smem (floats): W1T[64][148] @0, WkT[192][64] @9472, WT[32][64] @21760,
//                SX[NW][4*148] @23808, ACT[NW][4*64] @33280
#define A_W1   0
#define A_WK   9472
#define A_WT   21760
#define A_SX   23808
#define A_ACT  33280
#define A_SMEM_BYTES ((A_ACT + NW*TB*64)*4)   // 149504

__global__ void __launch_bounds__(512) kernelA(
    const float* __restrict__ x,  const float* __restrict__ W1, const float* __restrict__ b1,
    const float* __restrict__ Wk, const float* __restrict__ bk,
    const float* __restrict__ g1, const float* __restrict__ be1,
    const float* __restrict__ wrf)
{
    extern __shared__ float sm[];
    const int tid = threadIdx.x, lane = tid & 31, warp = tid >> 5;

    for (int idx = tid; idx < 64*148; idx += 512) {
        int c = idx / 148, i = idx - c*148;
        sm[A_W1 + c*148 + i] = (i < INDIM) ? W1[i*64 + c] : 0.f;
    }
    for (int idx = tid; idx < 192*64; idx += 512) {
        int c = idx >> 6, i = idx & 63;
        sm[A_WK + c*64 + i] = Wk[i*192 + c];
    }
    for (int idx = tid; idx < MF*DIM; idx += 512) sm[A_WT + idx] = wrf[idx];
    __syncthreads();

    // hoisted per-lane params
    const float b1l0 = b1[lane], b1l1 = b1[lane+32];
    float bkl[6];
#pragma unroll
    for (int c = 0; c < 6; c++) bkl[c] = bk[((c&1)?32:0) + (c>>1)*64 + lane];
    // bkl: 0->k lane, 1->k lane+32, 2->q lane, 3->q lane+32, 4->v lane, 5->v lane+32
    const float g1l0 = g1[lane], g1l1 = g1[lane+32];
    const float be1l0 = be1[lane], be1l1 = be1[lane+32];

    float* SX  = sm + A_SX  + warp*TB*148;
    float* ACT = sm + A_ACT + warp*TB*64;
    const float4* W1T4 = (const float4*)(sm + A_W1);
    const float4* WKT4 = (const float4*)(sm + A_WK);
    const float4* WT4  = (const float4*)(sm + A_WT);
    const float4* SX4  = (const float4*)SX;
    const float4* ACT4 = (const float4*)ACT;
    const float inv64 = 1.0f/64.0f;
    const float rsM   = 0.17677669529663689f;

    for (long long base = (long long)(blockIdx.x*NW + warp)*TB; base < NTOK;
         base += (long long)gridDim.x*NW*TB) {
#pragma unroll
        for (int t = 0; t < TB; t++) {
            const float* xr = x + (base + t)*INDIM;
            for (int i = lane; i < 148; i += 32) SX[t*148 + i] = (i < INDIM) ? xr[i] : 0.f;
        }
        __syncwarp();

        // ---- h = x @ W1 + b1 ----
        float hh[TB][2];
#pragma unroll
        for (int t = 0; t < TB; t++) { hh[t][0] = b1l0; hh[t][1] = b1l1; }
        for (int j = 0; j < 37; j++) {
            float4 w0 = W1T4[lane*37 + j];
            float4 w1 = W1T4[(lane+32)*37 + j];
#pragma unroll
            for (int t = 0; t < TB; t++) {
                float4 xv = SX4[t*37 + j];
                hh[t][0] = dot4(xv, w0, hh[t][0]);
                hh[t][1] = dot4(xv, w1, hh[t][1]);
            }
        }
        // ---- LN1 ----
#pragma unroll
        for (int t = 0; t < TB; t++) {
            float mu  = wsum(hh[t][0] + hh[t][1]) * inv64;
            float d0 = hh[t][0] - mu, d1 = hh[t][1] - mu;
            float var = wsum(d0*d0 + d1*d1) * inv64;
            float inv = rsqrtf(var + 1e-5f);
            ACT[t*64 + lane]      = d0*inv*g1l0 + be1l0;
            ACT[t*64 + lane + 32] = d1*inv*g1l1 + be1l1;
        }
        __syncwarp();

        // ---- kqv ----
        float kk[TB][2], qq[TB][2], vv[TB][2];
#pragma unroll
        for (int t = 0; t < TB; t++) {
            kk[t][0]=bkl[0]; kk[t][1]=bkl[1];
            qq[t][0]=bkl[2]; qq[t][1]=bkl[3];
            vv[t][0]=bkl[4]; vv[t][1]=bkl[5];
        }
        for (int j = 0; j < 16; j++) {
            float4 wk0 = WKT4[(lane     )*16 + j];
            float4 wk1 = WKT4[(lane + 32)*16 + j];
            float4 wq0 = WKT4[(lane + 64)*16 + j];
            float4 wq1 = WKT4[(lane + 96)*16 + j];
            float4 wv0 = WKT4[(lane +128)*16 + j];
            float4 wv1 = WKT4[(lane +160)*16 + j];
#pragma unroll
            for (int t = 0; t < TB; t++) {
                float4 a = ACT4[t*16 + j];
                kk[t][0] = dot4(a, wk0, kk[t][0]);
                kk[t][1] = dot4(a, wk1, kk[t][1]);
                qq[t][0] = dot4(a, wq0, qq[t][0]);
                qq[t][1] = dot4(a, wq1, qq[t][1]);
                vv[t][0] = dot4(a, wv0, vv[t][0]);
                vv[t][1] = dot4(a, wv1, vv[t][1]);
            }
        }

        // ---- kp ----
        float xd[TB];
#pragma unroll
        for (int t = 0; t < TB; t++)
            xd[t] = 0.5f * wsum(kk[t][0]*kk[t][0] + kk[t][1]*kk[t][1]);
        __syncwarp();
#pragma unroll
        for (int t = 0; t < TB; t++) { ACT[t*64+lane]=kk[t][0]; ACT[t*64+lane+32]=kk[t][1]; }
        __syncwarp();
        float pk[TB] = {0.f,0.f,0.f,0.f};
        for (int j = 0; j < 16; j++) {
            float4 wv = WT4[lane*16 + j];
#pragma unroll
            for (int t = 0; t < TB; t++) pk[t] = dot4(ACT4[t*16 + j], wv, pk[t]);
        }
#pragma unroll
        for (int t = 0; t < TB; t++)
            d_kp[(base + t)*MF + lane] = expf(pk[t] - xd[t]) * rsM;

        // ---- qp ----
#pragma unroll
        for (int t = 0; t < TB; t++)
            xd[t] = 0.5f * wsum(qq[t][0]*qq[t][0] + qq[t][1]*qq[t][1]);
        __syncwarp();
#pragma unroll
        for (int t = 0; t < TB; t++) { ACT[t*64+lane]=qq[t][0]; ACT[t*64+lane+32]=qq[t][1]; }
        __syncwarp();
        float pq[TB] = {0.f,0.f,0.f,0.f};
        for (int j = 0; j < 16; j++) {
            float4 wv = WT4[lane*16 + j];
#pragma unroll
            for (int t = 0; t < TB; t++) pq[t] = dot4(ACT4[t*16 + j], wv, pq[t]);
        }
#pragma unroll
        for (int t = 0; t < TB; t++)
            d_qp[(base + t)*MF + lane] = expf(pq[t] - xd[t]) * rsM;

        // ---- v ----
#pragma unroll
        for (int t = 0; t < TB; t++) {
            d_v[(base + t)*64 + lane]      = vv[t][0];
            d_v[(base + t)*64 + lane + 32] = vv[t][1];
        }
        __syncwarp();
    }
}

// ===================== zero =====================
__global__ void kernelZero() {
    int i = blockIdx.x*blockDim.x + threadIdx.x;
    if (i < BATCH*MF)     d_kpsum[i] = 0.f;
    if (i < BATCH*DIM*MF) d_kptv[i]  = 0.f;
}

// ===================== Kernel B =====================
#define B_TILE 8
__global__ void __launch_bounds__(256) kernelB()
{
    __shared__ float sv [B_TILE*64];
    __shared__ float skp[B_TILE*32];
    const int tid = threadIdx.x;
    const int b   = blockIdx.y;
    const int m   = tid & 31, dg = tid >> 5;

    float acc[8];
#pragma unroll
    for (int j = 0; j < 8; j++) acc[j] = 0.f;
    float ks = 0.f;

    const int t0 = blockIdx.x * (TSEQ/8);
    const int t1 = t0 + (TSEQ/8);          // 392 = 49 * 8
    for (int base = t0; base < t1; base += B_TILE) {
        __syncthreads();
        {
            const float4* src = (const float4*)(d_v + ((long long)(b*TSEQ + base))*64);
            float4* dst = (float4*)sv;
            if (tid < B_TILE*16) dst[tid] = src[tid];
            const float4* srck = (const float4*)(d_kp + ((long long)(b*TSEQ + base))*32);
            float4* dstk = (float4*)skp;
            if (tid < B_TILE*8) dstk[tid] = srck[tid];
        }
        __syncthreads();
#pragma unroll
        for (int tt = 0; tt < B_TILE; tt++) {
            float kpm = skp[tt*32 + m];
#pragma unroll
            for (int j = 0; j < 8; j++)
                acc[j] = fmaf(kpm, sv[tt*64 + dg*8 + j], acc[j]);
            if (dg == 0) ks += kpm;
        }
    }
#pragma unroll
    for (int j = 0; j < 8; j++)
        atomicAdd(&d_kptv[b*2048 + (dg*8 + j)*32 + m], acc[j]);
    if (dg == 0) atomicAdd(&d_kpsum[b*32 + m], ks);
}

// ===================== Kernel C =====================
// smem (floats): W2T @0 (4096), Wm1T @4096, Wm2T @8192, KPTV[d][m] @12288 (2048),
//                KPS @14336 (32), ACT[NW][256] @14368, QP[NW][128] @18464
#define C_W2    0
#define C_WM1   4096
#define C_WM2   8192
#define C_KPTV  12288
#define C_KPS   14336
#define C_ACT   14368
#define C_QP    (C_ACT + NW*TB*64)
#define C_SMEM_BYTES ((C_QP + NW*TB*32)*4)   // 82048

__global__ void __launch_bounds__(512) kernelC(
    const float* __restrict__ W2,  const float* __restrict__ b2,
    const float* __restrict__ g2,  const float* __restrict__ be2,
    const float* __restrict__ Wm1, const float* __restrict__ bm1,
    const float* __restrict__ Wm2, const float* __restrict__ bm2,
    float* __restrict__ out)
{
    extern __shared__ float sm[];
    const int tid = threadIdx.x, lane = tid & 31, warp = tid >> 5;
    const int b = blockIdx.y;

    for (int idx = tid; idx < 4096; idx += 512) {
        int c = idx >> 6, i = idx & 63;
        sm[C_W2  + c*64 + i] = W2 [i*64 + c];
        sm[C_WM1 + c*64 + i] = Wm1[i*64 + c];
        sm[C_WM2 + c*64 + i] = Wm2[i*64 + c];
    }
    for (int i = tid; i < 2048; i += 512) sm[C_KPTV + i] = d_kptv[b*2048 + i];
    if (tid < 32) sm[C_KPS + tid] = d_kpsum[b*32 + tid];
    __syncthreads();

    const float b2l0 = b2[lane], b2l1 = b2[lane+32];
    const float g2l0 = g2[lane], g2l1 = g2[lane+32];
    const float be2l0 = be2[lane], be2l1 = be2[lane+32];
    const float bm1l0 = bm1[lane], bm1l1 = bm1[lane+32];
    const float bm2l0 = bm2[lane], bm2l1 = bm2[lane+32];
    const float kpsl = sm[C_KPS + lane];

    float* ACT = sm + C_ACT + warp*TB*64;
    float* QP  = sm + C_QP  + warp*TB*32;
    const float4* W2T4  = (const float4*)(sm + C_W2);
    const float4* WM1T4 = (const float4*)(sm + C_WM1);
    const float4* WM2T4 = (const float4*)(sm + C_WM2);
    const float4* KPTV4 = (const float4*)(sm + C_KPTV);
    const float4* ACT4  = (const float4*)ACT;
    const float4* QP4   = (const float4*)QP;
    const float inv64 = 1.0f/64.0f;

    for (int lt = (blockIdx.x*NW + warp)*TB; lt < TSEQ; lt += gridDim.x*NW*TB) {
        const long long tok0 = (long long)b*TSEQ + lt;

        float rD[TB];
#pragma unroll
        for (int t = 0; t < TB; t++) {
            float qpv = d_qp[(tok0 + t)*MF + lane];
            QP[t*32 + lane] = qpv;
            float D = wsum(qpv * kpsl);
            rD[t] = 1.0f / (D + 1e-8f);
        }
        __syncwarp();

        // att = qp @ kptv^T  (cols = d)
        float aa[TB][2];
#pragma unroll
        for (int t = 0; t < TB; t++) { aa[t][0] = 0.f; aa[t][1] = 0.f; }
        for (int j = 0; j < 8; j++) {
            float4 w0 = KPTV4[lane*8 + j];
            float4 w1 = KPTV4[(lane+32)*8 + j];
#pragma unroll
            for (int t = 0; t < TB; t++) {
                float4 q4 = QP4[t*8 + j];
                aa[t][0] = dot4(q4, w0, aa[t][0]);
                aa[t][1] = dot4(q4, w1, aa[t][1]);
            }
        }
        __syncwarp();
#pragma unroll
        for (int t = 0; t < TB; t++) {
            ACT[t*64 + lane]      = aa[t][0] * rD[t];
            ACT[t*64 + lane + 32] = aa[t][1] * rD[t];
        }
        __syncwarp();

        // y = v + att @ W2 + b2
        float yy[TB][2];
#pragma unroll
        for (int t = 0; t < TB; t++) {
            yy[t][0] = d_v[(tok0 + t)*64 + lane]      + b2l0;
            yy[t][1] = d_v[(tok0 + t)*64 + lane + 32] + b2l1;
        }
        for (int j = 0; j < 16; j++) {
            float4 w0 = W2T4[lane*16 + j];
            float4 w1 = W2T4[(lane+32)*16 + j];
#pragma unroll
            for (int t = 0; t < TB; t++) {
                float4 a = ACT4[t*16 + j];
                yy[t][0] = dot4(a, w0, yy[t][0]);
                yy[t][1] = dot4(a, w1, yy[t][1]);
            }
        }

        // LN2 -> ACT
        __syncwarp();
#pragma unroll
        for (int t = 0; t < TB; t++) {
            float mu  = wsum(yy[t][0] + yy[t][1]) * inv64;
            float d0 = yy[t][0] - mu, d1 = yy[t][1] - mu;
            float var = wsum(d0*d0 + d1*d1) * inv64;
            float inv = rsqrtf(var + 1e-5f);
            ACT[t*64 + lane]      = d0*inv*g2l0 + be2l0;
            ACT[t*64 + lane + 32] = d1*inv*g2l1 + be2l1;
        }
        __syncwarp();

        // m1 + GELU -> ACT
        float zz[TB][2];
#pragma unroll
        for (int t = 0; t < TB; t++) { zz[t][0] = bm1l0; zz[t][1] = bm1l1; }
        for (int j = 0; j < 16; j++) {
            float4 w0 = WM1T4[lane*16 + j];
            float4 w1 = WM1T4[(lane+32)*16 + j];
#pragma unroll
            for (int t = 0; t < TB; t++) {
                float4 a = ACT4[t*16 + j];
                zz[t][0] = dot4(a, w0, zz[t][0]);
                zz[t][1] = dot4(a, w1, zz[t][1]);
            }
        }
        __syncwarp();
#pragma unroll
        for (int t = 0; t < TB; t++) {
            float z0 = zz[t][0], z1 = zz[t][1];
            ACT[t*64 + lane]      = 0.5f*z0*(1.0f + erff(z0*0.70710678118654752f));
            ACT[t*64 + lane + 32] = 0.5f*z1*(1.0f + erff(z1*0.70710678118654752f));
        }
        __syncwarp();

        // m2 + residual -> out
        float oo[TB][2];
#pragma unroll
        for (int t = 0; t < TB; t++) { oo[t][0] = bm2l0; oo[t][1] = bm2l1; }
        for (int j = 0; j < 16; j++) {
            float4 w0 = WM2T4[lane*16 + j];
            float4 w1 = WM2T4[(lane+32)*16 + j];
#pragma unroll
            for (int t = 0; t < TB; t++) {
                float4 a = ACT4[t*16 + j];
                oo[t][0] = dot4(a, w0, oo[t][0]);
                oo[t][1] = dot4(a, w1, oo[t][1]);
            }
        }
#pragma unroll
        for (int t = 0; t < TB; t++) {
            out[(tok0 + t)*64 + lane]      = yy[t][0] + oo[t][0];
            out[(tok0 + t)*64 + lane + 32] = yy[t][1] + oo[t][1];
        }
        __syncwarp();
    }
}

// ===================== launch =====================
extern "C" void kernel_launch(void* const* d_in, const int* in_sizes, int n_in,
                              void* d_out, int out_size)
{
    const float* x   = (const float*)d_in[0];
    const float* W1  = (const float*)d_in[1];
    const float* b1  = (const float*)d_in[2];
    const float* Wk  = (const float*)d_in[3];
    const float* bk  = (const float*)d_in[4];
    const float* W2  = (const float*)d_in[5];
    const float* b2  = (const float*)d_in[6];
    const float* g1  = (const float*)d_in[7];
    const float* be1 = (const float*)d_in[8];
    const float* g2  = (const float*)d_in[9];
    const float* be2 = (const float*)d_in[10];
    const float* Wm1 = (const float*)d_in[11];
    const float* bm1 = (const float*)d_in[12];
    const float* Wm2 = (const float*)d_in[13];
    const float* bm2 = (const float*)d_in[14];
    const float* wrf = (const float*)d_in[15];
    float* out = (float*)d_out;

    cudaFuncSetAttribute(kernelA, cudaFuncAttributeMaxDynamicSharedMemorySize, A_SMEM_BYTES);
    cudaFuncSetAttribute(kernelC, cudaFuncAttributeMaxDynamicSharedMemorySize, C_SMEM_BYTES);

    kernelA<<<148, 512, A_SMEM_BYTES>>>(x, W1, b1, Wk, bk, g1, be1, wrf);
    kernelZero<<<(BATCH*DIM*MF + 255)/256, 256>>>();
    kernelB<<<dim3(8, BATCH), 256>>>();
    kernelC<<<dim3(7, BATCH), 512, C_SMEM_BYTES>>>(W2, b2, g2, be2, Wm1, bm1, Wm2, bm2, out);
}

// round 6
// speedup vs baseline: 2.1422x; 1.4150x over previous
#include <cuda_runtime.h>
#include <math.h>

#define BATCH  64
#define TSEQ   3136
#define NTOK   (BATCH*TSEQ)   // 200704
#define INDIM  147
#define DIM    64
#define MF     32
#define TB     8              // tokens per warp
#define NW     16             // warps per block (512 threads)

// -------- scratch --------
__device__ float d_v [NTOK*DIM];
__device__ float d_kp[NTOK*MF];
__device__ float d_qp[NTOK*MF];
__device__ float d_kpsum[BATCH*MF];
__device__ float d_kptv [BATCH*DIM*MF];

__device__ __forceinline__ float wsum(float v) {
#pragma unroll
    for (int o = 16; o; o >>= 1) v += __shfl_xor_sync(0xffffffffu, v, o);
    return v;
}
__device__ __forceinline__ float dot4(float4 a, float4 b, float acc) {
    acc = fmaf(a.x, b.x, acc); acc = fmaf(a.y, b.y, acc);
    acc = fmaf(a.z, b.z, acc); acc = fmaf(a.w, b.w, acc);
    return acc;
}

// ===================== Kernel A =====================
// smem floats: W1T[64][148] @0, WkT[192][64] @9472, WT[32][64] @21760,
//              SX[NW][8*148] @23808, ACT[NW][8*64] @42752  -> 50944 floats (203.8KB)
#define A_W1   0
#define A_WK   9472
#define A_WT   21760
#define A_SX   23808
#define A_ACT  (A_SX + NW*TB*148)
#define A_SMEM_BYTES ((A_ACT + NW*TB*64)*4)

__global__ void __launch_bounds__(512) kernelA(
    const float* __restrict__ x,  const float* __restrict__ W1, const float* __restrict__ b1,
    const float* __restrict__ Wk, const float* __restrict__ bk,
    const float* __restrict__ g1, const float* __restrict__ be1,
    const float* __restrict__ wrf)
{
    extern __shared__ float sm[];
    const int tid = threadIdx.x, lane = tid & 31, warp = tid >> 5;

    for (int idx = tid; idx < 64*148; idx += 512) {
        int c = idx / 148, i = idx - c*148;
        sm[A_W1 + c*148 + i] = (i < INDIM) ? W1[i*64 + c] : 0.f;
    }
    for (int idx = tid; idx < 192*64; idx += 512) {
        int c = idx >> 6, i = idx & 63;
        sm[A_WK + c*64 + i] = Wk[i*192 + c];
    }
    for (int idx = tid; idx < MF*DIM; idx += 512) sm[A_WT + idx] = wrf[idx];
    __syncthreads();

    const float b1l0 = b1[lane], b1l1 = b1[lane+32];
    float bkl[6];
#pragma unroll
    for (int c = 0; c < 6; c++) bkl[c] = bk[((c&1)?32:0) + (c>>1)*64 + lane];
    const float g1l0 = g1[lane], g1l1 = g1[lane+32];
    const float be1l0 = be1[lane], be1l1 = be1[lane+32];

    float* SX  = sm + A_SX  + warp*TB*148;
    float* ACT = sm + A_ACT + warp*TB*64;
    const float4* W1T4 = (const float4*)(sm + A_W1);
    const float4* WKT4 = (const float4*)(sm + A_WK);
    const float4* WT4  = (const float4*)(sm + A_WT);
    const float4* SX4  = (const float4*)SX;
    const float4* ACT4 = (const float4*)ACT;
    const float inv64 = 1.0f/64.0f;
    const float rsM   = 0.17677669529663689f;

    for (long long base = (long long)(blockIdx.x*NW + warp)*TB; base < NTOK;
         base += (long long)gridDim.x*NW*TB) {
#pragma unroll
        for (int t = 0; t < TB; t++) {
            const float* xr = x + (base + t)*INDIM;
            for (int i = lane; i < 148; i += 32) SX[t*148 + i] = (i < INDIM) ? xr[i] : 0.f;
        }
        __syncwarp();

        // ---- h = x @ W1 + b1 ----
        float hh[TB][2];
#pragma unroll
        for (int t = 0; t < TB; t++) { hh[t][0] = b1l0; hh[t][1] = b1l1; }
#pragma unroll 2
        for (int j = 0; j < 37; j++) {
            float4 w0 = W1T4[lane*37 + j];
            float4 w1 = W1T4[(lane+32)*37 + j];
#pragma unroll
            for (int t = 0; t < TB; t++) {
                float4 xv = SX4[t*37 + j];
                hh[t][0] = dot4(xv, w0, hh[t][0]);
                hh[t][1] = dot4(xv, w1, hh[t][1]);
            }
        }
        // ---- LN1 ----
#pragma unroll
        for (int t = 0; t < TB; t++) {
            float mu  = wsum(hh[t][0] + hh[t][1]) * inv64;
            float d0 = hh[t][0] - mu, d1 = hh[t][1] - mu;
            float var = wsum(d0*d0 + d1*d1) * inv64;
            float inv = rsqrtf(var + 1e-5f);
            ACT[t*64 + lane]      = d0*inv*g1l0 + be1l0;
            ACT[t*64 + lane + 32] = d1*inv*g1l1 + be1l1;
        }
        __syncwarp();

        // ---- kqv ----
        float kk[TB][2], qq[TB][2], vv[TB][2];
#pragma unroll
        for (int t = 0; t < TB; t++) {
            kk[t][0]=bkl[0]; kk[t][1]=bkl[1];
            qq[t][0]=bkl[2]; qq[t][1]=bkl[3];
            vv[t][0]=bkl[4]; vv[t][1]=bkl[5];
        }
#pragma unroll 2
        for (int j = 0; j < 16; j++) {
            float4 wk0 = WKT4[(lane     )*16 + j];
            float4 wk1 = WKT4[(lane + 32)*16 + j];
            float4 wq0 = WKT4[(lane + 64)*16 + j];
            float4 wq1 = WKT4[(lane + 96)*16 + j];
            float4 wv0 = WKT4[(lane +128)*16 + j];
            float4 wv1 = WKT4[(lane +160)*16 + j];
#pragma unroll
            for (int t = 0; t < TB; t++) {
                float4 a = ACT4[t*16 + j];
                kk[t][0] = dot4(a, wk0, kk[t][0]);
                kk[t][1] = dot4(a, wk1, kk[t][1]);
                qq[t][0] = dot4(a, wq0, qq[t][0]);
                qq[t][1] = dot4(a, wq1, qq[t][1]);
                vv[t][0] = dot4(a, wv0, vv[t][0]);
                vv[t][1] = dot4(a, wv1, vv[t][1]);
            }
        }

        // ---- kp ----
        float xd[TB];
#pragma unroll
        for (int t = 0; t < TB; t++)
            xd[t] = 0.5f * wsum(kk[t][0]*kk[t][0] + kk[t][1]*kk[t][1]);
        __syncwarp();
#pragma unroll
        for (int t = 0; t < TB; t++) { ACT[t*64+lane]=kk[t][0]; ACT[t*64+lane+32]=kk[t][1]; }
        __syncwarp();
        float pk[TB];
#pragma unroll
        for (int t = 0; t < TB; t++) pk[t] = 0.f;
#pragma unroll 2
        for (int j = 0; j < 16; j++) {
            float4 wv = WT4[lane*16 + j];
#pragma unroll
            for (int t = 0; t < TB; t++) pk[t] = dot4(ACT4[t*16 + j], wv, pk[t]);
        }
#pragma unroll
        for (int t = 0; t < TB; t++)
            d_kp[(base + t)*MF + lane] = expf(pk[t] - xd[t]) * rsM;

        // ---- qp ----
#pragma unroll
        for (int t = 0; t < TB; t++)
            xd[t] = 0.5f * wsum(qq[t][0]*qq[t][0] + qq[t][1]*qq[t][1]);
        __syncwarp();
#pragma unroll
        for (int t = 0; t < TB; t++) { ACT[t*64+lane]=qq[t][0]; ACT[t*64+lane+32]=qq[t][1]; }
        __syncwarp();
        float pq[TB];
#pragma unroll
        for (int t = 0; t < TB; t++) pq[t] = 0.f;
#pragma unroll 2
        for (int j = 0; j < 16; j++) {
            float4 wv = WT4[lane*16 + j];
#pragma unroll
            for (int t = 0; t < TB; t++) pq[t] = dot4(ACT4[t*16 + j], wv, pq[t]);
        }
#pragma unroll
        for (int t = 0; t < TB; t++)
            d_qp[(base + t)*MF + lane] = expf(pq[t] - xd[t]) * rsM;

        // ---- v ----
#pragma unroll
        for (int t = 0; t < TB; t++) {
            d_v[(base + t)*64 + lane]      = vv[t][0];
            d_v[(base + t)*64 + lane + 32] = vv[t][1];
        }
        __syncwarp();
    }
}

// ===================== zero =====================
__global__ void kernelZero() {
    int i = blockIdx.x*blockDim.x + threadIdx.x;
    if (i < BATCH*MF)     d_kpsum[i] = 0.f;
    if (i < BATCH*DIM*MF) d_kptv[i]  = 0.f;
}

// ===================== Kernel B =====================
#define B_TILE 8
__global__ void __launch_bounds__(256) kernelB()
{
    __shared__ float sv [B_TILE*64];
    __shared__ float skp[B_TILE*32];
    const int tid = threadIdx.x;
    const int b   = blockIdx.y;
    const int m   = tid & 31, dg = tid >> 5;

    float acc[8];
#pragma unroll
    for (int j = 0; j < 8; j++) acc[j] = 0.f;
    float ks = 0.f;

    const int t0 = blockIdx.x * (TSEQ/8);
    const int t1 = t0 + (TSEQ/8);
    for (int base = t0; base < t1; base += B_TILE) {
        __syncthreads();
        {
            const float4* src = (const float4*)(d_v + ((long long)(b*TSEQ + base))*64);
            float4* dst = (float4*)sv;
            if (tid < B_TILE*16) dst[tid] = src[tid];
            const float4* srck = (const float4*)(d_kp + ((long long)(b*TSEQ + base))*32);
            float4* dstk = (float4*)skp;
            if (tid < B_TILE*8) dstk[tid] = srck[tid];
        }
        __syncthreads();
#pragma unroll
        for (int tt = 0; tt < B_TILE; tt++) {
            float kpm = skp[tt*32 + m];
#pragma unroll
            for (int j = 0; j < 8; j++)
                acc[j] = fmaf(kpm, sv[tt*64 + dg*8 + j], acc[j]);
            if (dg == 0) ks += kpm;
        }
    }
#pragma unroll
    for (int j = 0; j < 8; j++)
        atomicAdd(&d_kptv[b*2048 + (dg*8 + j)*32 + m], acc[j]);
    if (dg == 0) atomicAdd(&d_kpsum[b*32 + m], ks);
}

// ===================== Kernel C =====================
// smem floats: W2T @0 (4096), Wm1T @4096, Wm2T @8192, KPTV @12288 (2048),
//              KPS @14336 (32), ACT @14368 (NW*8*64=8192), QP @22560 (NW*8*32=4096)
#define C_W2    0
#define C_WM1   4096
#define C_WM2   8192
#define C_KPTV  12288
#define C_KPS   14336
#define C_ACT   14368
#define C_QP    (C_ACT + NW*TB*64)
#define C_SMEM_BYTES ((C_QP + NW*TB*32)*4)

__global__ void __launch_bounds__(512) kernelC(
    const float* __restrict__ W2,  const float* __restrict__ b2,
    const float* __restrict__ g2,  const float* __restrict__ be2,
    const float* __restrict__ Wm1, const float* __restrict__ bm1,
    const float* __restrict__ Wm2, const float* __restrict__ bm2,
    float* __restrict__ out)
{
    extern __shared__ float sm[];
    const int tid = threadIdx.x, lane = tid & 31, warp = tid >> 5;
    const int b = blockIdx.y;

    for (int idx = tid; idx < 4096; idx += 512) {
        int c = idx >> 6, i = idx & 63;
        sm[C_W2  + c*64 + i] = W2 [i*64 + c];
        sm[C_WM1 + c*64 + i] = Wm1[i*64 + c];
        sm[C_WM2 + c*64 + i] = Wm2[i*64 + c];
    }
    for (int i = tid; i < 2048; i += 512) sm[C_KPTV + i] = d_kptv[b*2048 + i];
    if (tid < 32) sm[C_KPS + tid] = d_kpsum[b*32 + tid];
    __syncthreads();

    const float b2l0 = b2[lane], b2l1 = b2[lane+32];
    const float g2l0 = g2[lane], g2l1 = g2[lane+32];
    const float be2l0 = be2[lane], be2l1 = be2[lane+32];
    const float bm1l0 = bm1[lane], bm1l1 = bm1[lane+32];
    const float bm2l0 = bm2[lane], bm2l1 = bm2[lane+32];
    const float kpsl = sm[C_KPS + lane];

    float* ACT = sm + C_ACT + warp*TB*64;
    float* QP  = sm + C_QP  + warp*TB*32;
    const float4* W2T4  = (const float4*)(sm + C_W2);
    const float4* WM1T4 = (const float4*)(sm + C_WM1);
    const float4* WM2T4 = (const float4*)(sm + C_WM2);
    const float4* KPTV4 = (const float4*)(sm + C_KPTV);
    const float4* ACT4  = (const float4*)ACT;
    const float4* QP4   = (const float4*)QP;
    const float inv64 = 1.0f/64.0f;

    for (int lt = (blockIdx.x*NW + warp)*TB; lt < TSEQ; lt += gridDim.x*NW*TB) {
        const long long tok0 = (long long)b*TSEQ + lt;

        float rD[TB];
#pragma unroll
        for (int t = 0; t < TB; t++) {
            float qpv = d_qp[(tok0 + t)*MF + lane];
            QP[t*32 + lane] = qpv;
            float D = wsum(qpv * kpsl);
            rD[t] = 1.0f / (D + 1e-8f);
        }
        __syncwarp();

        // att = qp @ kptv^T
        float aa[TB][2];
#pragma unroll
        for (int t = 0; t < TB; t++) { aa[t][0] = 0.f; aa[t][1] = 0.f; }
#pragma unroll 2
        for (int j = 0; j < 8; j++) {
            float4 w0 = KPTV4[lane*8 + j];
            float4 w1 = KPTV4[(lane+32)*8 + j];
#pragma unroll
            for (int t = 0; t < TB; t++) {
                float4 q4 = QP4[t*8 + j];
                aa[t][0] = dot4(q4, w0, aa[t][0]);
                aa[t][1] = dot4(q4, w1, aa[t][1]);
            }
        }
        __syncwarp();
#pragma unroll
        for (int t = 0; t < TB; t++) {
            ACT[t*64 + lane]      = aa[t][0] * rD[t];
            ACT[t*64 + lane + 32] = aa[t][1] * rD[t];
        }
        __syncwarp();

        // y = v + att @ W2 + b2
        float yy[TB][2];
#pragma unroll
        for (int t = 0; t < TB; t++) {
            yy[t][0] = d_v[(tok0 + t)*64 + lane]      + b2l0;
            yy[t][1] = d_v[(tok0 + t)*64 + lane + 32] + b2l1;
        }
#pragma unroll 2
        for (int j = 0; j < 16; j++) {
            float4 w0 = W2T4[lane*16 + j];
            float4 w1 = W2T4[(lane+32)*16 + j];
#pragma unroll
            for (int t = 0; t < TB; t++) {
                float4 a = ACT4[t*16 + j];
                yy[t][0] = dot4(a, w0, yy[t][0]);
                yy[t][1] = dot4(a, w1, yy[t][1]);
            }
        }

        // LN2 -> ACT
        __syncwarp();
#pragma unroll
        for (int t = 0; t < TB; t++) {
            float mu  = wsum(yy[t][0] + yy[t][1]) * inv64;
            float d0 = yy[t][0] - mu, d1 = yy[t][1] - mu;
            float var = wsum(d0*d0 + d1*d1) * inv64;
            float inv = rsqrtf(var + 1e-5f);
            ACT[t*64 + lane]      = d0*inv*g2l0 + be2l0;
            ACT[t*64 + lane + 32] = d1*inv*g2l1 + be2l1;
        }
        __syncwarp();

        // m1 + GELU -> ACT
        float zz[TB][2];
#pragma unroll
        for (int t = 0; t < TB; t++) { zz[t][0] = bm1l0; zz[t][1] = bm1l1; }
#pragma unroll 2
        for (int j = 0; j < 16; j++) {
            float4 w0 = WM1T4[lane*16 + j];
            float4 w1 = WM1T4[(lane+32)*16 + j];
#pragma unroll
            for (int t = 0; t < TB; t++) {
                float4 a = ACT4[t*16 + j];
                zz[t][0] = dot4(a, w0, zz[t][0]);
                zz[t][1] = dot4(a, w1, zz[t][1]);
            }
        }
        __syncwarp();
#pragma unroll
        for (int t = 0; t < TB; t++) {
            float z0 = zz[t][0], z1 = zz[t][1];
            ACT[t*64 + lane]      = 0.5f*z0*(1.0f + erff(z0*0.70710678118654752f));
            ACT[t*64 + lane + 32] = 0.5f*z1*(1.0f + erff(z1*0.70710678118654752f));
        }
        __syncwarp();

        // m2 + residual -> out
        float oo[TB][2];
#pragma unroll
        for (int t = 0; t < TB; t++) { oo[t][0] = bm2l0; oo[t][1] = bm2l1; }
#pragma unroll 2
        for (int j = 0; j < 16; j++) {
            float4 w0 = WM2T4[lane*16 + j];
            float4 w1 = WM2T4[(lane+32)*16 + j];
#pragma unroll
            for (int t = 0; t < TB; t++) {
                float4 a = ACT4[t*16 + j];
                oo[t][0] = dot4(a, w0, oo[t][0]);
                oo[t][1] = dot4(a, w1, oo[t][1]);
            }
        }
#pragma unroll
        for (int t = 0; t < TB; t++) {
            out[(tok0 + t)*64 + lane]      = yy[t][0] + oo[t][0];
            out[(tok0 + t)*64 + lane + 32] = yy[t][1] + oo[t][1];
        }
        __syncwarp();
    }
}

// ===================== launch =====================
extern "C" void kernel_launch(void* const* d_in, const int* in_sizes, int n_in,
                              void* d_out, int out_size)
{
    const float* x   = (const float*)d_in[0];
    const float* W1  = (const float*)d_in[1];
    const float* b1  = (const float*)d_in[2];
    const float* Wk  = (const float*)d_in[3];
    const float* bk  = (const float*)d_in[4];
    const float* W2  = (const float*)d_in[5];
    const float* b2  = (const float*)d_in[6];
    const float* g1  = (const float*)d_in[7];
    const float* be1 = (const float*)d_in[8];
    const float* g2  = (const float*)d_in[9];
    const float* be2 = (const float*)d_in[10];
    const float* Wm1 = (const float*)d_in[11];
    const float* bm1 = (const float*)d_in[12];
    const float* Wm2 = (const float*)d_in[13];
    const float* bm2 = (const float*)d_in[14];
    const float* wrf = (const float*)d_in[15];
    float* out = (float*)d_out;

    cudaFuncSetAttribute(kernelA, cudaFuncAttributeMaxDynamicSharedMemorySize, A_SMEM_BYTES);
    cudaFuncSetAttribute(kernelC, cudaFuncAttributeMaxDynamicSharedMemorySize, C_SMEM_BYTES);

    kernelA<<<148, 512, A_SMEM_BYTES>>>(x, W1, b1, Wk, bk, g1, be1, wrf);
    kernelZero<<<(BATCH*DIM*MF + 255)/256, 256>>>();
    kernelB<<<dim3(8, BATCH), 256>>>();
    kernelC<<<dim3(7, BATCH), 512, C_SMEM_BYTES>>>(W2, b2, g2, be2, Wm1, bm1, Wm2, bm2, out);
}

// round 7
// speedup vs baseline: 2.3448x; 1.0946x over previous
#include <cuda_runtime.h>
#include <math.h>

#define BATCH  64
#define TSEQ   3136
#define NTOK   (BATCH*TSEQ)   // 200704
#define INDIM  147
#define DIM    64
#define MF     32
#define TB     8              // tokens per warp
#define NW     16             // warps per block (512 threads)

#define WPAD   68             // padded floats per weight column (17 float4, odd -> conflict-free)
#define WPAD4  17
#define KPAD   36             // padded floats per kptv row (9 float4)
#define KPAD4  9

// -------- scratch --------
__device__ float d_v [NTOK*DIM];
__device__ float d_kp[NTOK*MF];
__device__ float d_qp[NTOK*MF];
__device__ float d_kpsum[BATCH*MF];
__device__ float d_kptv [BATCH*DIM*MF];

__device__ __forceinline__ float wsum(float v) {
#pragma unroll
    for (int o = 16; o; o >>= 1) v += __shfl_xor_sync(0xffffffffu, v, o);
    return v;
}
__device__ __forceinline__ float dot4(float4 a, float4 b, float acc) {
    acc = fmaf(a.x, b.x, acc); acc = fmaf(a.y, b.y, acc);
    acc = fmaf(a.z, b.z, acc); acc = fmaf(a.w, b.w, acc);
    return acc;
}

// ===================== Kernel A =====================
// smem floats: W1T[64][148] @0 (9472), WkT[192][68] @9472 (13056), WT[32][68] @22528 (2176),
//              SX[NW][8*148] @24704 (18944), ACT[NW][8*64] @43648 (8192) -> 51840 floats (207.4KB)
#define A_W1   0
#define A_WK   9472
#define A_WT   (A_WK + 192*WPAD)
#define A_SX   (A_WT + 32*WPAD)
#define A_ACT  (A_SX + NW*TB*148)
#define A_SMEM_BYTES ((A_ACT + NW*TB*64)*4)

__global__ void __launch_bounds__(512) kernelA(
    const float* __restrict__ x,  const float* __restrict__ W1, const float* __restrict__ b1,
    const float* __restrict__ Wk, const float* __restrict__ bk,
    const float* __restrict__ g1, const float* __restrict__ be1,
    const float* __restrict__ wrf)
{
    extern __shared__ float sm[];
    const int tid = threadIdx.x, lane = tid & 31, warp = tid >> 5;

    for (int idx = tid; idx < 64*148; idx += 512) {
        int c = idx / 148, i = idx - c*148;
        sm[A_W1 + c*148 + i] = (i < INDIM) ? W1[i*64 + c] : 0.f;
    }
    for (int idx = tid; idx < 192*64; idx += 512) {
        int c = idx >> 6, i = idx & 63;
        sm[A_WK + c*WPAD + i] = Wk[i*192 + c];
    }
    for (int idx = tid; idx < MF*DIM; idx += 512) {
        int m = idx >> 6, d = idx & 63;
        sm[A_WT + m*WPAD + d] = wrf[m*64 + d];
    }
    __syncthreads();

    const float b1l0 = b1[lane], b1l1 = b1[lane+32];
    float bkl[6];
#pragma unroll
    for (int c = 0; c < 6; c++) bkl[c] = bk[((c&1)?32:0) + (c>>1)*64 + lane];
    const float g1l0 = g1[lane], g1l1 = g1[lane+32];
    const float be1l0 = be1[lane], be1l1 = be1[lane+32];

    float* SX  = sm + A_SX  + warp*TB*148;
    float* ACT = sm + A_ACT + warp*TB*64;
    const float4* W1T4 = (const float4*)(sm + A_W1);
    const float4* WKT4 = (const float4*)(sm + A_WK);
    const float4* WT4  = (const float4*)(sm + A_WT);
    const float4* SX4  = (const float4*)SX;
    const float4* ACT4 = (const float4*)ACT;
    const float inv64 = 1.0f/64.0f;
    const float rsM   = 0.17677669529663689f;

    for (long long base = (long long)(blockIdx.x*NW + warp)*TB; base < NTOK;
         base += (long long)gridDim.x*NW*TB) {
#pragma unroll
        for (int t = 0; t < TB; t++) {
            const float* xr = x + (base + t)*INDIM;
            for (int i = lane; i < 148; i += 32) SX[t*148 + i] = (i < INDIM) ? xr[i] : 0.f;
        }
        __syncwarp();

        // ---- h = x @ W1 + b1 ----
        float hh[TB][2];
#pragma unroll
        for (int t = 0; t < TB; t++) { hh[t][0] = b1l0; hh[t][1] = b1l1; }
#pragma unroll 2
        for (int j = 0; j < 37; j++) {
            float4 w0 = W1T4[lane*37 + j];
            float4 w1 = W1T4[(lane+32)*37 + j];
#pragma unroll
            for (int t = 0; t < TB; t++) {
                float4 xv = SX4[t*37 + j];
                hh[t][0] = dot4(xv, w0, hh[t][0]);
                hh[t][1] = dot4(xv, w1, hh[t][1]);
            }
        }
        // ---- LN1 ----
#pragma unroll
        for (int t = 0; t < TB; t++) {
            float mu  = wsum(hh[t][0] + hh[t][1]) * inv64;
            float d0 = hh[t][0] - mu, d1 = hh[t][1] - mu;
            float var = wsum(d0*d0 + d1*d1) * inv64;
            float inv = rsqrtf(var + 1e-5f);
            ACT[t*64 + lane]      = d0*inv*g1l0 + be1l0;
            ACT[t*64 + lane + 32] = d1*inv*g1l1 + be1l1;
        }
        __syncwarp();

        // ---- kqv ----
        float kk[TB][2], qq[TB][2], vv[TB][2];
#pragma unroll
        for (int t = 0; t < TB; t++) {
            kk[t][0]=bkl[0]; kk[t][1]=bkl[1];
            qq[t][0]=bkl[2]; qq[t][1]=bkl[3];
            vv[t][0]=bkl[4]; vv[t][1]=bkl[5];
        }
#pragma unroll 2
        for (int j = 0; j < 16; j++) {
            float4 wk0 = WKT4[(lane     )*WPAD4 + j];
            float4 wk1 = WKT4[(lane + 32)*WPAD4 + j];
            float4 wq0 = WKT4[(lane + 64)*WPAD4 + j];
            float4 wq1 = WKT4[(lane + 96)*WPAD4 + j];
            float4 wv0 = WKT4[(lane +128)*WPAD4 + j];
            float4 wv1 = WKT4[(lane +160)*WPAD4 + j];
#pragma unroll
            for (int t = 0; t < TB; t++) {
                float4 a = ACT4[t*16 + j];
                kk[t][0] = dot4(a, wk0, kk[t][0]);
                kk[t][1] = dot4(a, wk1, kk[t][1]);
                qq[t][0] = dot4(a, wq0, qq[t][0]);
                qq[t][1] = dot4(a, wq1, qq[t][1]);
                vv[t][0] = dot4(a, wv0, vv[t][0]);
                vv[t][1] = dot4(a, wv1, vv[t][1]);
            }
        }

        // ---- kp ----
        float xd[TB];
#pragma unroll
        for (int t = 0; t < TB; t++)
            xd[t] = 0.5f * wsum(kk[t][0]*kk[t][0] + kk[t][1]*kk[t][1]);
        __syncwarp();
#pragma unroll
        for (int t = 0; t < TB; t++) { ACT[t*64+lane]=kk[t][0]; ACT[t*64+lane+32]=kk[t][1]; }
        __syncwarp();
        float pk[TB];
#pragma unroll
        for (int t = 0; t < TB; t++) pk[t] = 0.f;
#pragma unroll 2
        for (int j = 0; j < 16; j++) {
            float4 wv = WT4[lane*WPAD4 + j];
#pragma unroll
            for (int t = 0; t < TB; t++) pk[t] = dot4(ACT4[t*16 + j], wv, pk[t]);
        }
#pragma unroll
        for (int t = 0; t < TB; t++)
            d_kp[(base + t)*MF + lane] = __expf(pk[t] - xd[t]) * rsM;

        // ---- qp ----
#pragma unroll
        for (int t = 0; t < TB; t++)
            xd[t] = 0.5f * wsum(qq[t][0]*qq[t][0] + qq[t][1]*qq[t][1]);
        __syncwarp();
#pragma unroll
        for (int t = 0; t < TB; t++) { ACT[t*64+lane]=qq[t][0]; ACT[t*64+lane+32]=qq[t][1]; }
        __syncwarp();
        float pq[TB];
#pragma unroll
        for (int t = 0; t < TB; t++) pq[t] = 0.f;
#pragma unroll 2
        for (int j = 0; j < 16; j++) {
            float4 wv = WT4[lane*WPAD4 + j];
#pragma unroll
            for (int t = 0; t < TB; t++) pq[t] = dot4(ACT4[t*16 + j], wv, pq[t]);
        }
#pragma unroll
        for (int t = 0; t < TB; t++)
            d_qp[(base + t)*MF + lane] = __expf(pq[t] - xd[t]) * rsM;

        // ---- v ----
#pragma unroll
        for (int t = 0; t < TB; t++) {
            d_v[(base + t)*64 + lane]      = vv[t][0];
            d_v[(base + t)*64 + lane + 32] = vv[t][1];
        }
        __syncwarp();
    }
}

// ===================== zero =====================
__global__ void kernelZero() {
    int i = blockIdx.x*blockDim.x + threadIdx.x;
    if (i < BATCH*MF)     d_kpsum[i] = 0.f;
    if (i < BATCH*DIM*MF) d_kptv[i]  = 0.f;
}

// ===================== Kernel B =====================
#define B_TILE 8
__global__ void __launch_bounds__(256) kernelB()
{
    __shared__ float sv [B_TILE*64];
    __shared__ float skp[B_TILE*32];
    const int tid = threadIdx.x;
    const int b   = blockIdx.y;
    const int m   = tid & 31, dg = tid >> 5;

    float acc[8];
#pragma unroll
    for (int j = 0; j < 8; j++) acc[j] = 0.f;
    float ks = 0.f;

    const int t0 = blockIdx.x * (TSEQ/8);
    const int t1 = t0 + (TSEQ/8);
    for (int base = t0; base < t1; base += B_TILE) {
        __syncthreads();
        {
            const float4* src = (const float4*)(d_v + ((long long)(b*TSEQ + base))*64);
            float4* dst = (float4*)sv;
            if (tid < B_TILE*16) dst[tid] = src[tid];
            const float4* srck = (const float4*)(d_kp + ((long long)(b*TSEQ + base))*32);
            float4* dstk = (float4*)skp;
            if (tid < B_TILE*8) dstk[tid] = srck[tid];
        }
        __syncthreads();
#pragma unroll
        for (int tt = 0; tt < B_TILE; tt++) {
            float kpm = skp[tt*32 + m];
#pragma unroll
            for (int j = 0; j < 8; j++)
                acc[j] = fmaf(kpm, sv[tt*64 + dg*8 + j], acc[j]);
            if (dg == 0) ks += kpm;
        }
    }
#pragma unroll
    for (int j = 0; j < 8; j++)
        atomicAdd(&d_kptv[b*2048 + (dg*8 + j)*32 + m], acc[j]);
    if (dg == 0) atomicAdd(&d_kpsum[b*32 + m], ks);
}

// ===================== Kernel C =====================
// smem floats: W2T[64][68] @0 (4352), Wm1T @4352, Wm2T @8704, KPTV[64][36] @13056 (2304),
//              KPS @15360 (32), ACT @15392 (8192), QP @23584 (4096) -> 27680 floats (110.7KB)
#define C_W2    0
#define C_WM1   (C_W2 + 64*WPAD)
#define C_WM2   (C_WM1 + 64*WPAD)
#define C_KPTV  (C_WM2 + 64*WPAD)
#define C_KPS   (C_KPTV + 64*KPAD)
#define C_ACT   (C_KPS + 32)
#define C_QP    (C_ACT + NW*TB*64)
#define C_SMEM_BYTES ((C_QP + NW*TB*32)*4)

__global__ void __launch_bounds__(512) kernelC(
    const float* __restrict__ W2,  const float* __restrict__ b2,
    const float* __restrict__ g2,  const float* __restrict__ be2,
    const float* __restrict__ Wm1, const float* __restrict__ bm1,
    const float* __restrict__ Wm2, const float* __restrict__ bm2,
    float* __restrict__ out)
{
    extern __shared__ float sm[];
    const int tid = threadIdx.x, lane = tid & 31, warp = tid >> 5;
    const int b = blockIdx.y;

    for (int idx = tid; idx < 4096; idx += 512) {
        int c = idx >> 6, i = idx & 63;
        sm[C_W2  + c*WPAD + i] = W2 [i*64 + c];
        sm[C_WM1 + c*WPAD + i] = Wm1[i*64 + c];
        sm[C_WM2 + c*WPAD + i] = Wm2[i*64 + c];
    }
    for (int i = tid; i < 2048; i += 512) {
        int d = i >> 5, m = i & 31;
        sm[C_KPTV + d*KPAD + m] = d_kptv[b*2048 + i];
    }
    if (tid < 32) sm[C_KPS + tid] = d_kpsum[b*32 + tid];
    __syncthreads();

    const float b2l0 = b2[lane], b2l1 = b2[lane+32];
    const float g2l0 = g2[lane], g2l1 = g2[lane+32];
    const float be2l0 = be2[lane], be2l1 = be2[lane+32];
    const float bm1l0 = bm1[lane], bm1l1 = bm1[lane+32];
    const float bm2l0 = bm2[lane], bm2l1 = bm2[lane+32];
    const float kpsl = sm[C_KPS + lane];

    float* ACT = sm + C_ACT + warp*TB*64;
    float* QP  = sm + C_QP  + warp*TB*32;
    const float4* W2T4  = (const float4*)(sm + C_W2);
    const float4* WM1T4 = (const float4*)(sm + C_WM1);
    const float4* WM2T4 = (const float4*)(sm + C_WM2);
    const float4* KPTV4 = (const float4*)(sm + C_KPTV);
    const float4* ACT4  = (const float4*)ACT;
    const float4* QP4   = (const float4*)QP;
    const float inv64 = 1.0f/64.0f;

    for (int lt = (blockIdx.x*NW + warp)*TB; lt < TSEQ; lt += gridDim.x*NW*TB) {
        const long long tok0 = (long long)b*TSEQ + lt;

        float rD[TB];
#pragma unroll
        for (int t = 0; t < TB; t++) {
            float qpv = d_qp[(tok0 + t)*MF + lane];
            QP[t*32 + lane] = qpv;
            float D = wsum(qpv * kpsl);
            rD[t] = 1.0f / (D + 1e-8f);
        }
        __syncwarp();

        // att = qp @ kptv^T
        float aa[TB][2];
#pragma unroll
        for (int t = 0; t < TB; t++) { aa[t][0] = 0.f; aa[t][1] = 0.f; }
#pragma unroll 2
        for (int j = 0; j < 8; j++) {
            float4 w0 = KPTV4[lane*KPAD4 + j];
            float4 w1 = KPTV4[(lane+32)*KPAD4 + j];
#pragma unroll
            for (int t = 0; t < TB; t++) {
                float4 q4 = QP4[t*8 + j];
                aa[t][0] = dot4(q4, w0, aa[t][0]);
                aa[t][1] = dot4(q4, w1, aa[t][1]);
            }
        }
        __syncwarp();
#pragma unroll
        for (int t = 0; t < TB; t++) {
            ACT[t*64 + lane]      = aa[t][0] * rD[t];
            ACT[t*64 + lane + 32] = aa[t][1] * rD[t];
        }
        __syncwarp();

        // y = v + att @ W2 + b2
        float yy[TB][2];
#pragma unroll
        for (int t = 0; t < TB; t++) {
            yy[t][0] = d_v[(tok0 + t)*64 + lane]      + b2l0;
            yy[t][1] = d_v[(tok0 + t)*64 + lane + 32] + b2l1;
        }
#pragma unroll 2
        for (int j = 0; j < 16; j++) {
            float4 w0 = W2T4[lane*WPAD4 + j];
            float4 w1 = W2T4[(lane+32)*WPAD4 + j];
#pragma unroll
            for (int t = 0; t < TB; t++) {
                float4 a = ACT4[t*16 + j];
                yy[t][0] = dot4(a, w0, yy[t][0]);
                yy[t][1] = dot4(a, w1, yy[t][1]);
            }
        }

        // LN2 -> ACT
        __syncwarp();
#pragma unroll
        for (int t = 0; t < TB; t++) {
            float mu  = wsum(yy[t][0] + yy[t][1]) * inv64;
            float d0 = yy[t][0] - mu, d1 = yy[t][1] - mu;
            float var = wsum(d0*d0 + d1*d1) * inv64;
            float inv = rsqrtf(var + 1e-5f);
            ACT[t*64 + lane]      = d0*inv*g2l0 + be2l0;
            ACT[t*64 + lane + 32] = d1*inv*g2l1 + be2l1;
        }
        __syncwarp();

        // m1 + GELU -> ACT
        float zz[TB][2];
#pragma unroll
        for (int t = 0; t < TB; t++) { zz[t][0] = bm1l0; zz[t][1] = bm1l1; }
#pragma unroll 2
        for (int j = 0; j < 16; j++) {
            float4 w0 = WM1T4[lane*WPAD4 + j];
            float4 w1 = WM1T4[(lane+32)*WPAD4 + j];
#pragma unroll
            for (int t = 0; t < TB; t++) {
                float4 a = ACT4[t*16 + j];
                zz[t][0] = dot4(a, w0, zz[t][0]);
                zz[t][1] = dot4(a, w1, zz[t][1]);
            }
        }
        __syncwarp();
#pragma unroll
        for (int t = 0; t < TB; t++) {
            float z0 = zz[t][0], z1 = zz[t][1];
            ACT[t*64 + lane]      = 0.5f*z0*(1.0f + erff(z0*0.70710678118654752f));
            ACT[t*64 + lane + 32] = 0.5f*z1*(1.0f + erff(z1*0.70710678118654752f));
        }
        __syncwarp();

        // m2 + residual -> out
        float oo[TB][2];
#pragma unroll
        for (int t = 0; t < TB; t++) { oo[t][0] = bm2l0; oo[t][1] = bm2l1; }
#pragma unroll 2
        for (int j = 0; j < 16; j++) {
            float4 w0 = WM2T4[lane*WPAD4 + j];
            float4 w1 = WM2T4[(lane+32)*WPAD4 + j];
#pragma unroll
            for (int t = 0; t < TB; t++) {
                float4 a = ACT4[t*16 + j];
                oo[t][0] = dot4(a, w0, oo[t][0]);
                oo[t][1] = dot4(a, w1, oo[t][1]);
            }
        }
#pragma unroll
        for (int t = 0; t < TB; t++) {
            out[(tok0 + t)*64 + lane]      = yy[t][0] + oo[t][0];
            out[(tok0 + t)*64 + lane + 32] = yy[t][1] + oo[t][1];
        }
        __syncwarp();
    }
}

// ===================== launch =====================
extern "C" void kernel_launch(void* const* d_in, const int* in_sizes, int n_in,
                              void* d_out, int out_size)
{
    const float* x   = (const float*)d_in[0];
    const float* W1  = (const float*)d_in[1];
    const float* b1  = (const float*)d_in[2];
    const float* Wk  = (const float*)d_in[3];
    const float* bk  = (const float*)d_in[4];
    const float* W2  = (const float*)d_in[5];
    const float* b2  = (const float*)d_in[6];
    const float* g1  = (const float*)d_in[7];
    const float* be1 = (const float*)d_in[8];
    const float* g2  = (const float*)d_in[9];
    const float* be2 = (const float*)d_in[10];
    const float* Wm1 = (const float*)d_in[11];
    const float* bm1 = (const float*)d_in[12];
    const float* Wm2 = (const float*)d_in[13];
    const float* bm2 = (const float*)d_in[14];
    const float* wrf = (const float*)d_in[15];
    float* out = (float*)d_out;

    cudaFuncSetAttribute(kernelA, cudaFuncAttributeMaxDynamicSharedMemorySize, A_SMEM_BYTES);
    cudaFuncSetAttribute(kernelC, cudaFuncAttributeMaxDynamicSharedMemorySize, C_SMEM_BYTES);

    kernelA<<<148, 512, A_SMEM_BYTES>>>(x, W1, b1, Wk, bk, g1, be1, wrf);
    kernelZero<<<(BATCH*DIM*MF + 255)/256, 256>>>();
    kernelB<<<dim3(8, BATCH), 256>>>();
    kernelC<<<dim3(14, BATCH), 512, C_SMEM_BYTES>>>(W2, b2, g2, be2, Wm1, bm1, Wm2, bm2, out);
}

// round 9
// speedup vs baseline: 3.6795x; 1.5692x over previous
#include <cuda_runtime.h>
#include <math.h>

#define BATCH  64
#define TSEQ   3136
#define NTOK   (BATCH*TSEQ)   // 200704
#define INDIM  147
#define DIM    64
#define MF     32
#define TB     8              // tokens per warp
#define NW     16             // warps per block (512 threads)

#define WPAD   68             // 17 float4, odd -> conflict-free
#define WPAD4  17
#define KPAD   36             // 9 float4
#define KPAD4  9

// -------- scratch --------
__device__ float d_v [NTOK*DIM];
__device__ float d_kp[NTOK*MF];
__device__ float d_qp[NTOK*MF];
__device__ float d_kpsum[BATCH*MF];
__device__ float d_kptv [BATCH*DIM*MF];

typedef unsigned long long u64t;

__device__ __forceinline__ float wsum(float v) {
#pragma unroll
    for (int o = 16; o; o >>= 1) v += __shfl_xor_sync(0xffffffffu, v, o);
    return v;
}
__device__ __forceinline__ float dot4(float4 a, float4 b, float acc) {
    acc = fmaf(a.x, b.x, acc); acc = fmaf(a.y, b.y, acc);
    acc = fmaf(a.z, b.z, acc); acc = fmaf(a.w, b.w, acc);
    return acc;
}
__device__ __forceinline__ u64t dup2(float a) {
    u64t r; asm("mov.b64 %0, {%1, %1};" : "=l"(r) : "f"(a)); return r;
}
__device__ __forceinline__ void up2(u64t v, float& a, float& b) {
    asm("mov.b64 {%0, %1}, %2;" : "=f"(a), "=f"(b) : "l"(v));
}
__device__ __forceinline__ u64t ffma2(u64t a, u64t b, u64t c) {
    u64t r; asm("fma.rn.f32x2 %0, %1, %2, %3;" : "=l"(r) : "l"(a), "l"(b), "l"(c));
    return r;
}
__device__ __forceinline__ void acc4(u64t w, ulonglong2 aA, ulonglong2 aB, u64t* acc) {
    acc[0] = ffma2(w, aA.x, acc[0]); acc[1] = ffma2(w, aA.y, acc[1]);
    acc[2] = ffma2(w, aB.x, acc[2]); acc[3] = ffma2(w, aB.y, acc[3]);
}

// ===================== Kernel A =====================
// smem floats: W1T[64][148] @0, WkT[192][68], WT[32][68],
//              SX[NW][8*148] ([t][i]), ACT[NW][64*8] ([i][t])
#define A_W1   0
#define A_WK   9472
#define A_WT   (A_WK + 192*WPAD)
#define A_SX   (A_WT + 32*WPAD)
#define A_ACT  (A_SX + NW*TB*148)
#define A_SMEM_BYTES ((A_ACT + NW*DIM*TB)*4)

__global__ void __launch_bounds__(512) kernelA(
    const float* __restrict__ x,  const float* __restrict__ W1, const float* __restrict__ b1,
    const float* __restrict__ Wk, const float* __restrict__ bk,
    const float* __restrict__ g1, const float* __restrict__ be1,
    const float* __restrict__ wrf)
{
    extern __shared__ float sm[];
    const int tid = threadIdx.x, lane = tid & 31, warp = tid >> 5;

    for (int idx = tid; idx < 64*148; idx += 512) {
        int c = idx / 148, i = idx - c*148;
        sm[A_W1 + c*148 + i] = (i < INDIM) ? W1[i*64 + c] : 0.f;
    }
    for (int idx = tid; idx < 192*64; idx += 512) {
        int c = idx >> 6, i = idx & 63;
        sm[A_WK + c*WPAD + i] = Wk[i*192 + c];
    }
    for (int idx = tid; idx < MF*DIM; idx += 512) {
        int m = idx >> 6, d = idx & 63;
        sm[A_WT + m*WPAD + d] = wrf[m*64 + d];
    }
    __syncthreads();

    const float b1l0 = b1[lane], b1l1 = b1[lane+32];
    float bkl[6];
#pragma unroll
    for (int c = 0; c < 6; c++) bkl[c] = bk[((c&1)?32:0) + (c>>1)*64 + lane];
    const float g1l0 = g1[lane], g1l1 = g1[lane+32];
    const float be1l0 = be1[lane], be1l1 = be1[lane+32];

    float* SX  = sm + A_SX  + warp*TB*148;
    float* ACT = sm + A_ACT + warp*DIM*TB;
    const float4* W1T4 = (const float4*)(sm + A_W1);
    const float4* WKT4 = (const float4*)(sm + A_WK);
    const float4* WT4  = (const float4*)(sm + A_WT);
    const float4* SX4  = (const float4*)SX;
    const float inv64 = 1.0f/64.0f;
    const float rsM   = 0.17677669529663689f;

    for (long long base = (long long)(blockIdx.x*NW + warp)*TB; base < NTOK;
         base += (long long)gridDim.x*NW*TB) {
#pragma unroll
        for (int t = 0; t < TB; t++) {
            const float* xr = x + (base + t)*INDIM;
            for (int i = lane; i < 148; i += 32) SX[t*148 + i] = (i < INDIM) ? xr[i] : 0.f;
        }
        __syncwarp();

        // ---- h = x @ W1 + b1 (scalar) ----
        float hh0[TB], hh1[TB];
#pragma unroll
        for (int t = 0; t < TB; t++) { hh0[t] = b1l0; hh1[t] = b1l1; }
#pragma unroll 2
        for (int j = 0; j < 37; j++) {
            float4 w0 = W1T4[lane*37 + j];
            float4 w1 = W1T4[(lane+32)*37 + j];
#pragma unroll
            for (int t = 0; t < TB; t++) {
                float4 xv = SX4[t*37 + j];
                hh0[t] = dot4(xv, w0, hh0[t]);
                hh1[t] = dot4(xv, w1, hh1[t]);
            }
        }
        // ---- LN1 -> ACT [i][t] ----
        float hn0[TB], hn1[TB];
#pragma unroll
        for (int t = 0; t < TB; t++) {
            float mu  = wsum(hh0[t] + hh1[t]) * inv64;
            float d0 = hh0[t] - mu, d1 = hh1[t] - mu;
            float var = wsum(d0*d0 + d1*d1) * inv64;
            float inv = rsqrtf(var + 1e-5f);
            hn0[t] = d0*inv*g1l0 + be1l0;
            hn1[t] = d1*inv*g1l1 + be1l1;
        }
        __syncwarp();
        *(float4*)(ACT + lane*TB)        = make_float4(hn0[0],hn0[1],hn0[2],hn0[3]);
        *(float4*)(ACT + lane*TB + 4)    = make_float4(hn0[4],hn0[5],hn0[6],hn0[7]);
        *(float4*)(ACT + (lane+32)*TB)   = make_float4(hn1[0],hn1[1],hn1[2],hn1[3]);
        *(float4*)(ACT + (lane+32)*TB+4) = make_float4(hn1[4],hn1[5],hn1[6],hn1[7]);
        __syncwarp();

        // ---- kqv (f32x2, token pairs) ----
        u64t ka[2][4], qa[2][4], va[2][4];
#pragma unroll
        for (int p = 0; p < 4; p++) {
            ka[0][p]=dup2(bkl[0]); ka[1][p]=dup2(bkl[1]);
            qa[0][p]=dup2(bkl[2]); qa[1][p]=dup2(bkl[3]);
            va[0][p]=dup2(bkl[4]); va[1][p]=dup2(bkl[5]);
        }
#pragma unroll 1
        for (int j = 0; j < 16; j++) {
            float4 wk0 = WKT4[(lane     )*WPAD4 + j];
            float4 wk1 = WKT4[(lane + 32)*WPAD4 + j];
            float4 wq0 = WKT4[(lane + 64)*WPAD4 + j];
            float4 wq1 = WKT4[(lane + 96)*WPAD4 + j];
            float4 wv0 = WKT4[(lane +128)*WPAD4 + j];
            float4 wv1 = WKT4[(lane +160)*WPAD4 + j];
#pragma unroll
            for (int e = 0; e < 4; e++) {
                ulonglong2 aA = *(const ulonglong2*)(ACT + (4*j+e)*TB);
                ulonglong2 aB = *(const ulonglong2*)(ACT + (4*j+e)*TB + 4);
                acc4(dup2(((const float*)&wk0)[e]), aA, aB, ka[0]);
                acc4(dup2(((const float*)&wk1)[e]), aA, aB, ka[1]);
                acc4(dup2(((const float*)&wq0)[e]), aA, aB, qa[0]);
                acc4(dup2(((const float*)&wq1)[e]), aA, aB, qa[1]);
                acc4(dup2(((const float*)&wv0)[e]), aA, aB, va[0]);
                acc4(dup2(((const float*)&wv1)[e]), aA, aB, va[1]);
            }
        }

        // ---- kp ----
        float kk0[TB], kk1[TB];
#pragma unroll
        for (int p = 0; p < 4; p++) {
            up2(ka[0][p], kk0[2*p], kk0[2*p+1]);
            up2(ka[1][p], kk1[2*p], kk1[2*p+1]);
        }
        float xdk[TB];
#pragma unroll
        for (int t = 0; t < TB; t++)
            xdk[t] = 0.5f * wsum(kk0[t]*kk0[t] + kk1[t]*kk1[t]);
        __syncwarp();
        *(float4*)(ACT + lane*TB)        = make_float4(kk0[0],kk0[1],kk0[2],kk0[3]);
        *(float4*)(ACT + lane*TB + 4)    = make_float4(kk0[4],kk0[5],kk0[6],kk0[7]);
        *(float4*)(ACT + (lane+32)*TB)   = make_float4(kk1[0],kk1[1],kk1[2],kk1[3]);
        *(float4*)(ACT + (lane+32)*TB+4) = make_float4(kk1[4],kk1[5],kk1[6],kk1[7]);
        __syncwarp();
        {
            u64t pa[4] = {0ull,0ull,0ull,0ull};
#pragma unroll 2
            for (int j = 0; j < 16; j++) {
                float4 w = WT4[lane*WPAD4 + j];
#pragma unroll
                for (int e = 0; e < 4; e++) {
                    ulonglong2 aA = *(const ulonglong2*)(ACT + (4*j+e)*TB);
                    ulonglong2 aB = *(const ulonglong2*)(ACT + (4*j+e)*TB + 4);
                    acc4(dup2(((const float*)&w)[e]), aA, aB, pa);
                }
            }
            float pk[TB];
#pragma unroll
            for (int p = 0; p < 4; p++) up2(pa[p], pk[2*p], pk[2*p+1]);
#pragma unroll
            for (int t = 0; t < TB; t++)
                d_kp[(base + t)*MF + lane] = __expf(pk[t] - xdk[t]) * rsM;
        }

        // ---- qp ----
        float qq0[TB], qq1[TB];
#pragma unroll
        for (int p = 0; p < 4; p++) {
            up2(qa[0][p], qq0[2*p], qq0[2*p+1]);
            up2(qa[1][p], qq1[2*p], qq1[2*p+1]);
        }
        float xdq[TB];
#pragma unroll
        for (int t = 0; t < TB; t++)
            xdq[t] = 0.5f * wsum(qq0[t]*qq0[t] + qq1[t]*qq1[t]);
        __syncwarp();
        *(float4*)(ACT + lane*TB)        = make_float4(qq0[0],qq0[1],qq0[2],qq0[3]);
        *(float4*)(ACT + lane*TB + 4)    = make_float4(qq0[4],qq0[5],qq0[6],qq0[7]);
        *(float4*)(ACT + (lane+32)*TB)   = make_float4(qq1[0],qq1[1],qq1[2],qq1[3]);
        *(float4*)(ACT + (lane+32)*TB+4) = make_float4(qq1[4],qq1[5],qq1[6],qq1[7]);
        __syncwarp();
        {
            u64t pa[4] = {0ull,0ull,0ull,0ull};
#pragma unroll 2
            for (int j = 0; j < 16; j++) {
                float4 w = WT4[lane*WPAD4 + j];
#pragma unroll
                for (int e = 0; e < 4; e++) {
                    ulonglong2 aA = *(const ulonglong2*)(ACT + (4*j+e)*TB);
                    ulonglong2 aB = *(const ulonglong2*)(ACT + (4*j+e)*TB + 4);
                    acc4(dup2(((const float*)&w)[e]), aA, aB, pa);
                }
            }
            float pq[TB];
#pragma unroll
            for (int p = 0; p < 4; p++) up2(pa[p], pq[2*p], pq[2*p+1]);
#pragma unroll
            for (int t = 0; t < TB; t++)
                d_qp[(base + t)*MF + lane] = __expf(pq[t] - xdq[t]) * rsM;
        }

        // ---- v ----
        float v0t[TB], v1t[TB];
#pragma unroll
        for (int p = 0; p < 4; p++) {
            up2(va[0][p], v0t[2*p], v0t[2*p+1]);
            up2(va[1][p], v1t[2*p], v1t[2*p+1]);
        }
#pragma unroll
        for (int t = 0; t < TB; t++) {
            d_v[(base + t)*64 + lane]      = v0t[t];
            d_v[(base + t)*64 + lane + 32] = v1t[t];
        }
        __syncwarp();
    }
}

// ===================== zero =====================
__global__ void kernelZero() {
    int i = blockIdx.x*blockDim.x + threadIdx.x;
    if (i < BATCH*MF)     d_kpsum[i] = 0.f;
    if (i < BATCH*DIM*MF) d_kptv[i]  = 0.f;
}

// ===================== Kernel B =====================
#define B_TILE 8
__global__ void __launch_bounds__(256) kernelB()
{
    __shared__ float sv [B_TILE*64];
    __shared__ float skp[B_TILE*32];
    const int tid = threadIdx.x;
    const int b   = blockIdx.y;
    const int m   = tid & 31, dg = tid >> 5;

    float acc[8];
#pragma unroll
    for (int j = 0; j < 8; j++) acc[j] = 0.f;
    float ks = 0.f;

    const int t0 = blockIdx.x * (TSEQ/8);
    const int t1 = t0 + (TSEQ/8);
    for (int base = t0; base < t1; base += B_TILE) {
        __syncthreads();
        {
            const float4* src = (const float4*)(d_v + ((long long)(b*TSEQ + base))*64);
            float4* dst = (float4*)sv;
            if (tid < B_TILE*16) dst[tid] = src[tid];
            const float4* srck = (const float4*)(d_kp + ((long long)(b*TSEQ + base))*32);
            float4* dstk = (float4*)skp;
            if (tid < B_TILE*8) dstk[tid] = srck[tid];
        }
        __syncthreads();
#pragma unroll
        for (int tt = 0; tt < B_TILE; tt++) {
            float kpm = skp[tt*32 + m];
#pragma unroll
            for (int j = 0; j < 8; j++)
                acc[j] = fmaf(kpm, sv[tt*64 + dg*8 + j], acc[j]);
            if (dg == 0) ks += kpm;
        }
    }
#pragma unroll
    for (int j = 0; j < 8; j++)
        atomicAdd(&d_kptv[b*2048 + (dg*8 + j)*32 + m], acc[j]);
    if (dg == 0) atomicAdd(&d_kpsum[b*32 + m], ks);
}

// ===================== Kernel C =====================
// smem floats: W2T[64][68], Wm1T, Wm2T, KPTV[64][36], KPS[32],
//              ACT[NW][64*8] ([i][t]), QP[NW][32*8] ([m][t])
#define C_W2    0
#define C_WM1   (C_W2 + 64*WPAD)
#define C_WM2   (C_WM1 + 64*WPAD)
#define C_KPTV  (C_WM2 + 64*WPAD)
#define C_KPS   (C_KPTV + 64*KPAD)
#define C_ACT   (C_KPS + 32)
#define C_QP    (C_ACT + NW*DIM*TB)
#define C_SMEM_BYTES ((C_QP + NW*MF*TB)*4)

__global__ void __launch_bounds__(512) kernelC(
    const float* __restrict__ W2,  const float* __restrict__ b2,
    const float* __restrict__ g2,  const float* __restrict__ be2,
    const float* __restrict__ Wm1, const float* __restrict__ bm1,
    const float* __restrict__ Wm2, const float* __restrict__ bm2,
    float* __restrict__ out)
{
    extern __shared__ float sm[];
    const int tid = threadIdx.x, lane = tid & 31, warp = tid >> 5;
    const int b = blockIdx.y;

    for (int idx = tid; idx < 4096; idx += 512) {
        int c = idx >> 6, i = idx & 63;
        sm[C_W2  + c*WPAD + i] = W2 [i*64 + c];
        sm[C_WM1 + c*WPAD + i] = Wm1[i*64 + c];
        sm[C_WM2 + c*WPAD + i] = Wm2[i*64 + c];
    }
    for (int i = tid; i < 2048; i += 512) {
        int d = i >> 5, m = i & 31;
        sm[C_KPTV + d*KPAD + m] = d_kptv[b*2048 + i];
    }
    if (tid < 32) sm[C_KPS + tid] = d_kpsum[b*32 + tid];
    __syncthreads();

    const float b2l0 = b2[lane], b2l1 = b2[lane+32];
    const float g2l0 = g2[lane], g2l1 = g2[lane+32];
    const float be2l0 = be2[lane], be2l1 = be2[lane+32];
    const float bm1l0 = bm1[lane], bm1l1 = bm1[lane+32];
    const float bm2l0 = bm2[lane], bm2l1 = bm2[lane+32];
    const float kpsl = sm[C_KPS + lane];

    float* ACT = sm + C_ACT + warp*DIM*TB;
    float* QP  = sm + C_QP  + warp*MF*TB;
    const float4* W2T4  = (const float4*)(sm + C_W2);
    const float4* WM1T4 = (const float4*)(sm + C_WM1);
    const float4* WM2T4 = (const float4*)(sm + C_WM2);
    const float4* KPTV4 = (const float4*)(sm + C_KPTV);
    const float inv64 = 1.0f/64.0f;

    for (int lt = (blockIdx.x*NW + warp)*TB; lt < TSEQ; lt += gridDim.x*NW*TB) {
        const long long tok0 = (long long)b*TSEQ + lt;

        float qpv[TB], rD[TB];
#pragma unroll
        for (int t = 0; t < TB; t++) {
            qpv[t] = d_qp[(tok0 + t)*MF + lane];
            float D = wsum(qpv[t] * kpsl);
            rD[t] = 1.0f / (D + 1e-8f);
        }
        __syncwarp();
        *(float4*)(QP + lane*TB)     = make_float4(qpv[0],qpv[1],qpv[2],qpv[3]);
        *(float4*)(QP + lane*TB + 4) = make_float4(qpv[4],qpv[5],qpv[6],qpv[7]);
        __syncwarp();

        // att = qp @ kptv^T (f32x2)
        u64t aacc[2][4];
#pragma unroll
        for (int p = 0; p < 4; p++) { aacc[0][p] = 0ull; aacc[1][p] = 0ull; }
#pragma unroll 2
        for (int j = 0; j < 8; j++) {
            float4 w0 = KPTV4[lane*KPAD4 + j];
            float4 w1 = KPTV4[(lane+32)*KPAD4 + j];
#pragma unroll
            for (int e = 0; e < 4; e++) {
                ulonglong2 aA = *(const ulonglong2*)(QP + (4*j+e)*TB);
                ulonglong2 aB = *(const ulonglong2*)(QP + (4*j+e)*TB + 4);
                acc4(dup2(((const float*)&w0)[e]), aA, aB, aacc[0]);
                acc4(dup2(((const float*)&w1)[e]), aA, aB, aacc[1]);
            }
        }
        float a0[TB], a1[TB];
#pragma unroll
        for (int p = 0; p < 4; p++) {
            up2(aacc[0][p], a0[2*p], a0[2*p+1]);
            up2(aacc[1][p], a1[2*p], a1[2*p+1]);
        }
        __syncwarp();
        *(float4*)(ACT + lane*TB)        = make_float4(a0[0]*rD[0],a0[1]*rD[1],a0[2]*rD[2],a0[3]*rD[3]);
        *(float4*)(ACT + lane*TB + 4)    = make_float4(a0[4]*rD[4],a0[5]*rD[5],a0[6]*rD[6],a0[7]*rD[7]);
        *(float4*)(ACT + (lane+32)*TB)   = make_float4(a1[0]*rD[0],a1[1]*rD[1],a1[2]*rD[2],a1[3]*rD[3]);
        *(float4*)(ACT + (lane+32)*TB+4) = make_float4(a1[4]*rD[4],a1[5]*rD[5],a1[6]*rD[6],a1[7]*rD[7]);
        __syncwarp();

        // y = v + att @ W2 + b2
        float v0t[TB], v1t[TB];
#pragma unroll
        for (int t = 0; t < TB; t++) {
            v0t[t] = d_v[(tok0 + t)*64 + lane];
            v1t[t] = d_v[(tok0 + t)*64 + lane + 32];
        }
        u64t ya[2][4];
#pragma unroll
        for (int p = 0; p < 4; p++) { ya[0][p] = dup2(b2l0); ya[1][p] = dup2(b2l1); }
#pragma unroll 2
        for (int j = 0; j < 16; j++) {
            float4 w0 = W2T4[lane*WPAD4 + j];
            float4 w1 = W2T4[(lane+32)*WPAD4 + j];
#pragma unroll
            for (int e = 0; e < 4; e++) {
                ulonglong2 aA = *(const ulonglong2*)(ACT + (4*j+e)*TB);
                ulonglong2 aB = *(const ulonglong2*)(ACT + (4*j+e)*TB + 4);
                acc4(dup2(((const float*)&w0)[e]), aA, aB, ya[0]);
                acc4(dup2(((const float*)&w1)[e]), aA, aB, ya[1]);
            }
        }
        float yy0[TB], yy1[TB];
#pragma unroll
        for (int p = 0; p < 4; p++) {
            up2(ya[0][p], yy0[2*p], yy0[2*p+1]);
            up2(ya[1][p], yy1[2*p], yy1[2*p+1]);
        }
#pragma unroll
        for (int t = 0; t < TB; t++) { yy0[t] += v0t[t]; yy1[t] += v1t[t]; }

        // LN2 -> ACT
        float yn0[TB], yn1[TB];
#pragma unroll
        for (int t = 0; t < TB; t++) {
            float mu  = wsum(yy0[t] + yy1[t]) * inv64;
            float d0 = yy0[t] - mu, d1 = yy1[t] - mu;
            float var = wsum(d0*d0 + d1*d1) * inv64;
            float inv = rsqrtf(var + 1e-5f);
            yn0[t] = d0*inv*g2l0 + be2l0;
            yn1[t] = d1*inv*g2l1 + be2l1;
        }
        __syncwarp();
        *(float4*)(ACT + lane*TB)        = make_float4(yn0[0],yn0[1],yn0[2],yn0[3]);
        *(float4*)(ACT + lane*TB + 4)    = make_float4(yn0[4],yn0[5],yn0[6],yn0[7]);
        *(float4*)(ACT + (lane+32)*TB)   = make_float4(yn1[0],yn1[1],yn1[2],yn1[3]);
        *(float4*)(ACT + (lane+32)*TB+4) = make_float4(yn1[4],yn1[5],yn1[6],yn1[7]);
        __syncwarp();

        // m1 + GELU -> ACT
        u64t za[2][4];
#pragma unroll
        for (int p = 0; p < 4; p++) { za[0][p] = dup2(bm1l0); za[1][p] = dup2(bm1l1); }
#pragma unroll 2
        for (int j = 0; j < 16; j++) {
            float4 w0 = WM1T4[lane*WPAD4 + j];
            float4 w1 = WM1T4[(lane+32)*WPAD4 + j];
#pragma unroll
            for (int e = 0; e < 4; e++) {
                ulonglong2 aA = *(const ulonglong2*)(ACT + (4*j+e)*TB);
                ulonglong2 aB = *(const ulonglong2*)(ACT + (4*j+e)*TB + 4);
                acc4(dup2(((const float*)&w0)[e]), aA, aB, za[0]);
                acc4(dup2(((const float*)&w1)[e]), aA, aB, za[1]);
            }
        }
        float ge0[TB], ge1[TB];
#pragma unroll
        for (int p = 0; p < 4; p++) {
            up2(za[0][p], ge0[2*p], ge0[2*p+1]);
            up2(za[1][p], ge1[2*p], ge1[2*p+1]);
        }
#pragma unroll
        for (int t = 0; t < TB; t++) {
            ge0[t] = 0.5f*ge0[t]*(1.0f + erff(ge0[t]*0.70710678118654752f));
            ge1[t] = 0.5f*ge1[t]*(1.0f + erff(ge1[t]*0.70710678118654752f));
        }
        __syncwarp();
        *(float4*)(ACT + lane*TB)        = make_float4(ge0[0],ge0[1],ge0[2],ge0[3]);
        *(float4*)(ACT + lane*TB + 4)    = make_float4(ge0[4],ge0[5],ge0[6],ge0[7]);
        *(float4*)(ACT + (lane+32)*TB)   = make_float4(ge1[0],ge1[1],ge1[2],ge1[3]);
        *(float4*)(ACT + (lane+32)*TB+4) = make_float4(ge1[4],ge1[5],ge1[6],ge1[7]);
        __syncwarp();

        // m2 + residual -> out
        u64t oa[2][4];
#pragma unroll
        for (int p = 0; p < 4; p++) { oa[0][p] = dup2(bm2l0); oa[1][p] = dup2(bm2l1); }
#pragma unroll 2
        for (int j = 0; j < 16; j++) {
            float4 w0 = WM2T4[lane*WPAD4 + j];
            float4 w1 = WM2T4[(lane+32)*WPAD4 + j];
#pragma unroll
            for (int e = 0; e < 4; e++) {
                ulonglong2 aA = *(const ulonglong2*)(ACT + (4*j+e)*TB);
                ulonglong2 aB = *(const ulonglong2*)(ACT + (4*j+e)*TB + 4);
                acc4(dup2(((const float*)&w0)[e]), aA, aB, oa[0]);
                acc4(dup2(((const float*)&w1)[e]), aA, aB, oa[1]);
            }
        }
        float o0[TB], o1[TB];
#pragma unroll
        for (int p = 0; p < 4; p++) {
            up2(oa[0][p], o0[2*p], o0[2*p+1]);
            up2(oa[1][p], o1[2*p], o1[2*p+1]);
        }
#pragma unroll
        for (int t = 0; t < TB; t++) {
            out[(tok0 + t)*64 + lane]      = yy0[t] + o0[t];
            out[(tok0 + t)*64 + lane + 32] = yy1[t] + o1[t];
        }
        __syncwarp();
    }
}

// ===================== launch =====================
extern "C" void kernel_launch(void* const* d_in, const int* in_sizes, int n_in,
                              void* d_out, int out_size)
{
    const float* x   = (const float*)d_in[0];
    const float* W1  = (const float*)d_in[1];
    const float* b1  = (const float*)d_in[2];
    const float* Wk  = (const float*)d_in[3];
    const float* bk  = (const float*)d_in[4];
    const float* W2  = (const float*)d_in[5];
    const float* b2  = (const float*)d_in[6];
    const float* g1  = (const float*)d_in[7];
    const float* be1 = (const float*)d_in[8];
    const float* g2  = (const float*)d_in[9];
    const float* be2 = (const float*)d_in[10];
    const float* Wm1 = (const float*)d_in[11];
    const float* bm1 = (const float*)d_in[12];
    const float* Wm2 = (const float*)d_in[13];
    const float* bm2 = (const float*)d_in[14];
    const float* wrf = (const float*)d_in[15];
    float* out = (float*)d_out;

    cudaFuncSetAttribute(kernelA, cudaFuncAttributeMaxDynamicSharedMemorySize, A_SMEM_BYTES);
    cudaFuncSetAttribute(kernelC, cudaFuncAttributeMaxDynamicSharedMemorySize, C_SMEM_BYTES);

    kernelA<<<148, 512, A_SMEM_BYTES>>>(x, W1, b1, Wk, bk, g1, be1, wrf);
    kernelZero<<<(BATCH*DIM*MF + 255)/256, 256>>>();
    kernelB<<<dim3(8, BATCH), 256>>>();
    kernelC<<<dim3(14, BATCH), 512, C_SMEM_BYTES>>>(W2, b2, g2, be2, Wm1, bm1, Wm2, bm2, out);
}

// round 10
// speedup vs baseline: 4.4820x; 1.2181x over previous
#include <cuda_runtime.h>
#include <math.h>

#define BATCH  64
#define TSEQ   3136
#define NTOK   (BATCH*TSEQ)   // 200704
#define INDIM  147
#define DIM    64
#define MF     32
#define TB     8              // tokens per warp
#define NW     16             // warps per block (512 threads)

#define WPAD   68             // 17 float4, odd -> conflict-free
#define WPAD4  17
#define KPAD   36             // 9 float4
#define KPAD4  9

// -------- scratch --------
__device__ float d_v [NTOK*DIM];
__device__ float d_kp[NTOK*MF];
__device__ float d_qp[NTOK*MF];
__device__ float d_kpsum[BATCH*MF];
__device__ float d_kptv [BATCH*DIM*MF];

typedef unsigned long long u64t;

__device__ __forceinline__ float wsum(float v) {
#pragma unroll
    for (int o = 16; o; o >>= 1) v += __shfl_xor_sync(0xffffffffu, v, o);
    return v;
}
__device__ __forceinline__ u64t dup2(float a) {
    u64t r; asm("mov.b64 %0, {%1, %1};" : "=l"(r) : "f"(a)); return r;
}
__device__ __forceinline__ void up2(u64t v, float& a, float& b) {
    asm("mov.b64 {%0, %1}, %2;" : "=f"(a), "=f"(b) : "l"(v));
}
__device__ __forceinline__ u64t ffma2(u64t a, u64t b, u64t c) {
    u64t r; asm("fma.rn.f32x2 %0, %1, %2, %3;" : "=l"(r) : "l"(a), "l"(b), "l"(c));
    return r;
}
__device__ __forceinline__ void acc4(u64t w, ulonglong2 aA, ulonglong2 aB, u64t* acc) {
    acc[0] = ffma2(w, aA.x, acc[0]); acc[1] = ffma2(w, aA.y, acc[1]);
    acc[2] = ffma2(w, aB.x, acc[2]); acc[3] = ffma2(w, aB.y, acc[3]);
}

// ===================== Kernel A =====================
// smem floats: W1T[64][148] @0, WkT[192][68], WT[32][68],
//              SXT[NW][148*8] ([i][t], stride 8), ACT[NW][64*8] ([i][t])
#define A_W1   0
#define A_WK   9472
#define A_WT   (A_WK + 192*WPAD)
#define A_SX   (A_WT + 32*WPAD)
#define A_ACT  (A_SX + NW*148*TB)
#define A_SMEM_BYTES ((A_ACT + NW*DIM*TB)*4)

__global__ void __launch_bounds__(512) kernelA(
    const float* __restrict__ x,  const float* __restrict__ W1, const float* __restrict__ b1,
    const float* __restrict__ Wk, const float* __restrict__ bk,
    const float* __restrict__ g1, const float* __restrict__ be1,
    const float* __restrict__ wrf)
{
    extern __shared__ float sm[];
    const int tid = threadIdx.x, lane = tid & 31, warp = tid >> 5;

    for (int idx = tid; idx < 64*148; idx += 512) {
        int c = idx / 148, i = idx - c*148;
        sm[A_W1 + c*148 + i] = (i < INDIM) ? W1[i*64 + c] : 0.f;
    }
    for (int idx = tid; idx < 192*64; idx += 512) {
        int c = idx >> 6, i = idx & 63;
        sm[A_WK + c*WPAD + i] = Wk[i*192 + c];
    }
    for (int idx = tid; idx < MF*DIM; idx += 512) {
        int m = idx >> 6, d = idx & 63;
        sm[A_WT + m*WPAD + d] = wrf[m*64 + d];
    }
    __syncthreads();

    const float b1l0 = b1[lane], b1l1 = b1[lane+32];
    float bkl[6];
#pragma unroll
    for (int c = 0; c < 6; c++) bkl[c] = bk[((c&1)?32:0) + (c>>1)*64 + lane];
    const float g1l0 = g1[lane], g1l1 = g1[lane+32];
    const float be1l0 = be1[lane], be1l1 = be1[lane+32];

    float* SXT = sm + A_SX  + warp*148*TB;   // [i][t], stride 8
    float* ACT = sm + A_ACT + warp*DIM*TB;   // [i][t], stride 8
    const float4* W1T4 = (const float4*)(sm + A_W1);
    const float4* WKT4 = (const float4*)(sm + A_WK);
    const float4* WT4  = (const float4*)(sm + A_WT);
    const float inv64 = 1.0f/64.0f;
    const float rsM   = 0.17677669529663689f;

    const int tl = lane >> 2;    // token 0..7 owned by this lane for loads
    const int il = lane & 3;     // i4 sub-index

    for (long long base = (long long)(blockIdx.x*NW + warp)*TB; base < NTOK;
         base += (long long)gridDim.x*NW*TB) {
        // ---- load x tile directly transposed: SXT[i][t] ----
        {
            const float* xr = x + (base + tl)*INDIM;
#pragma unroll
            for (int it = 0; it < 10; it++) {
                int i4 = il + 4*it;
                if (i4 <= 36) {
                    int i0 = 4*i4;
                    float v0 = xr[i0];
                    float v1 = xr[i0+1];
                    float v2 = xr[i0+2];
                    float v3 = (i0+3 < INDIM) ? xr[i0+3] : 0.f;
                    SXT[(i0  )*TB + tl] = v0;
                    SXT[(i0+1)*TB + tl] = v1;
                    SXT[(i0+2)*TB + tl] = v2;
                    SXT[(i0+3)*TB + tl] = v3;
                }
            }
        }
        __syncwarp();

        // ---- h = x @ W1 + b1 (f32x2) ----
        u64t ha[2][4];
#pragma unroll
        for (int p = 0; p < 4; p++) { ha[0][p] = dup2(b1l0); ha[1][p] = dup2(b1l1); }
#pragma unroll 1
        for (int j = 0; j < 37; j++) {
            float4 w0 = W1T4[lane*37 + j];
            float4 w1 = W1T4[(lane+32)*37 + j];
#pragma unroll
            for (int e = 0; e < 4; e++) {
                ulonglong2 aA = *(const ulonglong2*)(SXT + (4*j+e)*TB);
                ulonglong2 aB = *(const ulonglong2*)(SXT + (4*j+e)*TB + 4);
                acc4(dup2(((const float*)&w0)[e]), aA, aB, ha[0]);
                acc4(dup2(((const float*)&w1)[e]), aA, aB, ha[1]);
            }
        }
        float hh0[TB], hh1[TB];
#pragma unroll
        for (int p = 0; p < 4; p++) {
            up2(ha[0][p], hh0[2*p], hh0[2*p+1]);
            up2(ha[1][p], hh1[2*p], hh1[2*p+1]);
        }

        // ---- LN1 -> ACT [i][t] ----
        float hn0[TB], hn1[TB];
#pragma unroll
        for (int t = 0; t < TB; t++) {
            float mu  = wsum(hh0[t] + hh1[t]) * inv64;
            float d0 = hh0[t] - mu, d1 = hh1[t] - mu;
            float var = wsum(d0*d0 + d1*d1) * inv64;
            float inv = rsqrtf(var + 1e-5f);
            hn0[t] = d0*inv*g1l0 + be1l0;
            hn1[t] = d1*inv*g1l1 + be1l1;
        }
        __syncwarp();
        *(float4*)(ACT + lane*TB)        = make_float4(hn0[0],hn0[1],hn0[2],hn0[3]);
        *(float4*)(ACT + lane*TB + 4)    = make_float4(hn0[4],hn0[5],hn0[6],hn0[7]);
        *(float4*)(ACT + (lane+32)*TB)   = make_float4(hn1[0],hn1[1],hn1[2],hn1[3]);
        *(float4*)(ACT + (lane+32)*TB+4) = make_float4(hn1[4],hn1[5],hn1[6],hn1[7]);
        __syncwarp();

        // ---- kqv (f32x2, token pairs) ----
        u64t ka[2][4], qa[2][4], va[2][4];
#pragma unroll
        for (int p = 0; p < 4; p++) {
            ka[0][p]=dup2(bkl[0]); ka[1][p]=dup2(bkl[1]);
            qa[0][p]=dup2(bkl[2]); qa[1][p]=dup2(bkl[3]);
            va[0][p]=dup2(bkl[4]); va[1][p]=dup2(bkl[5]);
        }
#pragma unroll 1
        for (int j = 0; j < 16; j++) {
            float4 wk0 = WKT4[(lane     )*WPAD4 + j];
            float4 wk1 = WKT4[(lane + 32)*WPAD4 + j];
            float4 wq0 = WKT4[(lane + 64)*WPAD4 + j];
            float4 wq1 = WKT4[(lane + 96)*WPAD4 + j];
            float4 wv0 = WKT4[(lane +128)*WPAD4 + j];
            float4 wv1 = WKT4[(lane +160)*WPAD4 + j];
#pragma unroll
            for (int e = 0; e < 4; e++) {
                ulonglong2 aA = *(const ulonglong2*)(ACT + (4*j+e)*TB);
                ulonglong2 aB = *(const ulonglong2*)(ACT + (4*j+e)*TB + 4);
                acc4(dup2(((const float*)&wk0)[e]), aA, aB, ka[0]);
                acc4(dup2(((const float*)&wk1)[e]), aA, aB, ka[1]);
                acc4(dup2(((const float*)&wq0)[e]), aA, aB, qa[0]);
                acc4(dup2(((const float*)&wq1)[e]), aA, aB, qa[1]);
                acc4(dup2(((const float*)&wv0)[e]), aA, aB, va[0]);
                acc4(dup2(((const float*)&wv1)[e]), aA, aB, va[1]);
            }
        }

        // ---- kp ----
        float kk0[TB], kk1[TB];
#pragma unroll
        for (int p = 0; p < 4; p++) {
            up2(ka[0][p], kk0[2*p], kk0[2*p+1]);
            up2(ka[1][p], kk1[2*p], kk1[2*p+1]);
        }
        float xdk[TB];
#pragma unroll
        for (int t = 0; t < TB; t++)
            xdk[t] = 0.5f * wsum(kk0[t]*kk0[t] + kk1[t]*kk1[t]);
        __syncwarp();
        *(float4*)(ACT + lane*TB)        = make_float4(kk0[0],kk0[1],kk0[2],kk0[3]);
        *(float4*)(ACT + lane*TB + 4)    = make_float4(kk0[4],kk0[5],kk0[6],kk0[7]);
        *(float4*)(ACT + (lane+32)*TB)   = make_float4(kk1[0],kk1[1],kk1[2],kk1[3]);
        *(float4*)(ACT + (lane+32)*TB+4) = make_float4(kk1[4],kk1[5],kk1[6],kk1[7]);
        __syncwarp();
        {
            u64t pa[4] = {0ull,0ull,0ull,0ull};
#pragma unroll 2
            for (int j = 0; j < 16; j++) {
                float4 w = WT4[lane*WPAD4 + j];
#pragma unroll
                for (int e = 0; e < 4; e++) {
                    ulonglong2 aA = *(const ulonglong2*)(ACT + (4*j+e)*TB);
                    ulonglong2 aB = *(const ulonglong2*)(ACT + (4*j+e)*TB + 4);
                    acc4(dup2(((const float*)&w)[e]), aA, aB, pa);
                }
            }
            float pk[TB];
#pragma unroll
            for (int p = 0; p < 4; p++) up2(pa[p], pk[2*p], pk[2*p+1]);
#pragma unroll
            for (int t = 0; t < TB; t++)
                d_kp[(base + t)*MF + lane] = __expf(pk[t] - xdk[t]) * rsM;
        }

        // ---- qp ----
        float qq0[TB], qq1[TB];
#pragma unroll
        for (int p = 0; p < 4; p++) {
            up2(qa[0][p], qq0[2*p], qq0[2*p+1]);
            up2(qa[1][p], qq1[2*p], qq1[2*p+1]);
        }
        float xdq[TB];
#pragma unroll
        for (int t = 0; t < TB; t++)
            xdq[t] = 0.5f * wsum(qq0[t]*qq0[t] + qq1[t]*qq1[t]);
        __syncwarp();
        *(float4*)(ACT + lane*TB)        = make_float4(qq0[0],qq0[1],qq0[2],qq0[3]);
        *(float4*)(ACT + lane*TB + 4)    = make_float4(qq0[4],qq0[5],qq0[6],qq0[7]);
        *(float4*)(ACT + (lane+32)*TB)   = make_float4(qq1[0],qq1[1],qq1[2],qq1[3]);
        *(float4*)(ACT + (lane+32)*TB+4) = make_float4(qq1[4],qq1[5],qq1[6],qq1[7]);
        __syncwarp();
        {
            u64t pa[4] = {0ull,0ull,0ull,0ull};
#pragma unroll 2
            for (int j = 0; j < 16; j++) {
                float4 w = WT4[lane*WPAD4 + j];
#pragma unroll
                for (int e = 0; e < 4; e++) {
                    ulonglong2 aA = *(const ulonglong2*)(ACT + (4*j+e)*TB);
                    ulonglong2 aB = *(const ulonglong2*)(ACT + (4*j+e)*TB + 4);
                    acc4(dup2(((const float*)&w)[e]), aA, aB, pa);
                }
            }
            float pq[TB];
#pragma unroll
            for (int p = 0; p < 4; p++) up2(pa[p], pq[2*p], pq[2*p+1]);
#pragma unroll
            for (int t = 0; t < TB; t++)
                d_qp[(base + t)*MF + lane] = __expf(pq[t] - xdq[t]) * rsM;
        }

        // ---- v ----
        float v0t[TB], v1t[TB];
#pragma unroll
        for (int p = 0; p < 4; p++) {
            up2(va[0][p], v0t[2*p], v0t[2*p+1]);
            up2(va[1][p], v1t[2*p], v1t[2*p+1]);
        }
#pragma unroll
        for (int t = 0; t < TB; t++) {
            d_v[(base + t)*64 + lane]      = v0t[t];
            d_v[(base + t)*64 + lane + 32] = v1t[t];
        }
        __syncwarp();
    }
}

// ===================== zero =====================
__global__ void kernelZero() {
    int i = blockIdx.x*blockDim.x + threadIdx.x;
    if (i < BATCH*MF)     d_kpsum[i] = 0.f;
    if (i < BATCH*DIM*MF) d_kptv[i]  = 0.f;
}

// ===================== Kernel B =====================
#define B_TILE 8
__global__ void __launch_bounds__(256) kernelB()
{
    __shared__ float sv [B_TILE*64];
    __shared__ float skp[B_TILE*32];
    const int tid = threadIdx.x;
    const int b   = blockIdx.y;
    const int m   = tid & 31, dg = tid >> 5;

    float acc[8];
#pragma unroll
    for (int j = 0; j < 8; j++) acc[j] = 0.f;
    float ks = 0.f;

    const int t0 = blockIdx.x * (TSEQ/8);
    const int t1 = t0 + (TSEQ/8);
    for (int base = t0; base < t1; base += B_TILE) {
        __syncthreads();
        {
            const float4* src = (const float4*)(d_v + ((long long)(b*TSEQ + base))*64);
            float4* dst = (float4*)sv;
            if (tid < B_TILE*16) dst[tid] = src[tid];
            const float4* srck = (const float4*)(d_kp + ((long long)(b*TSEQ + base))*32);
            float4* dstk = (float4*)skp;
            if (tid < B_TILE*8) dstk[tid] = srck[tid];
        }
        __syncthreads();
#pragma unroll
        for (int tt = 0; tt < B_TILE; tt++) {
            float kpm = skp[tt*32 + m];
#pragma unroll
            for (int j = 0; j < 8; j++)
                acc[j] = fmaf(kpm, sv[tt*64 + dg*8 + j], acc[j]);
            if (dg == 0) ks += kpm;
        }
    }
#pragma unroll
    for (int j = 0; j < 8; j++)
        atomicAdd(&d_kptv[b*2048 + (dg*8 + j)*32 + m], acc[j]);
    if (dg == 0) atomicAdd(&d_kpsum[b*32 + m], ks);
}

// ===================== Kernel C =====================
#define C_W2    0
#define C_WM1   (C_W2 + 64*WPAD)
#define C_WM2   (C_WM1 + 64*WPAD)
#define C_KPTV  (C_WM2 + 64*WPAD)
#define C_KPS   (C_KPTV + 64*KPAD)
#define C_ACT   (C_KPS + 32)
#define C_QP    (C_ACT + NW*DIM*TB)
#define C_SMEM_BYTES ((C_QP + NW*MF*TB)*4)

__global__ void __launch_bounds__(512) kernelC(
    const float* __restrict__ W2,  const float* __restrict__ b2,
    const float* __restrict__ g2,  const float* __restrict__ be2,
    const float* __restrict__ Wm1, const float* __restrict__ bm1,
    const float* __restrict__ Wm2, const float* __restrict__ bm2,
    float* __restrict__ out)
{
    extern __shared__ float sm[];
    const int tid = threadIdx.x, lane = tid & 31, warp = tid >> 5;
    const int b = blockIdx.y;

    for (int idx = tid; idx < 4096; idx += 512) {
        int c = idx >> 6, i = idx & 63;
        sm[C_W2  + c*WPAD + i] = W2 [i*64 + c];
        sm[C_WM1 + c*WPAD + i] = Wm1[i*64 + c];
        sm[C_WM2 + c*WPAD + i] = Wm2[i*64 + c];
    }
    for (int i = tid; i < 2048; i += 512) {
        int d = i >> 5, m = i & 31;
        sm[C_KPTV + d*KPAD + m] = d_kptv[b*2048 + i];
    }
    if (tid < 32) sm[C_KPS + tid] = d_kpsum[b*32 + tid];
    __syncthreads();

    const float b2l0 = b2[lane], b2l1 = b2[lane+32];
    const float g2l0 = g2[lane], g2l1 = g2[lane+32];
    const float be2l0 = be2[lane], be2l1 = be2[lane+32];
    const float bm1l0 = bm1[lane], bm1l1 = bm1[lane+32];
    const float bm2l0 = bm2[lane], bm2l1 = bm2[lane+32];
    const float kpsl = sm[C_KPS + lane];

    float* ACT = sm + C_ACT + warp*DIM*TB;
    float* QP  = sm + C_QP  + warp*MF*TB;
    const float4* W2T4  = (const float4*)(sm + C_W2);
    const float4* WM1T4 = (const float4*)(sm + C_WM1);
    const float4* WM2T4 = (const float4*)(sm + C_WM2);
    const float4* KPTV4 = (const float4*)(sm + C_KPTV);
    const float inv64 = 1.0f/64.0f;

    for (int lt = (blockIdx.x*NW + warp)*TB; lt < TSEQ; lt += gridDim.x*NW*TB) {
        const long long tok0 = (long long)b*TSEQ + lt;

        float qpv[TB], rD[TB];
#pragma unroll
        for (int t = 0; t < TB; t++) {
            qpv[t] = d_qp[(tok0 + t)*MF + lane];
            float D = wsum(qpv[t] * kpsl);
            rD[t] = 1.0f / (D + 1e-8f);
        }
        __syncwarp();
        *(float4*)(QP + lane*TB)     = make_float4(qpv[0],qpv[1],qpv[2],qpv[3]);
        *(float4*)(QP + lane*TB + 4) = make_float4(qpv[4],qpv[5],qpv[6],qpv[7]);
        __syncwarp();

        // att = qp @ kptv^T (f32x2)
        u64t aacc[2][4];
#pragma unroll
        for (int p = 0; p < 4; p++) { aacc[0][p] = 0ull; aacc[1][p] = 0ull; }
#pragma unroll 2
        for (int j = 0; j < 8; j++) {
            float4 w0 = KPTV4[lane*KPAD4 + j];
            float4 w1 = KPTV4[(lane+32)*KPAD4 + j];
#pragma unroll
            for (int e = 0; e < 4; e++) {
                ulonglong2 aA = *(const ulonglong2*)(QP + (4*j+e)*TB);
                ulonglong2 aB = *(const ulonglong2*)(QP + (4*j+e)*TB + 4);
                acc4(dup2(((const float*)&w0)[e]), aA, aB, aacc[0]);
                acc4(dup2(((const float*)&w1)[e]), aA, aB, aacc[1]);
            }
        }
        float a0[TB], a1[TB];
#pragma unroll
        for (int p = 0; p < 4; p++) {
            up2(aacc[0][p], a0[2*p], a0[2*p+1]);
            up2(aacc[1][p], a1[2*p], a1[2*p+1]);
        }
        __syncwarp();
        *(float4*)(ACT + lane*TB)        = make_float4(a0[0]*rD[0],a0[1]*rD[1],a0[2]*rD[2],a0[3]*rD[3]);
        *(float4*)(ACT + lane*TB + 4)    = make_float4(a0[4]*rD[4],a0[5]*rD[5],a0[6]*rD[6],a0[7]*rD[7]);
        *(float4*)(ACT + (lane+32)*TB)   = make_float4(a1[0]*rD[0],a1[1]*rD[1],a1[2]*rD[2],a1[3]*rD[3]);
        *(float4*)(ACT + (lane+32)*TB+4) = make_float4(a1[4]*rD[4],a1[5]*rD[5],a1[6]*rD[6],a1[7]*rD[7]);
        __syncwarp();

        // y = v + att @ W2 + b2
        float v0t[TB], v1t[TB];
#pragma unroll
        for (int t = 0; t < TB; t++) {
            v0t[t] = d_v[(tok0 + t)*64 + lane];
            v1t[t] = d_v[(tok0 + t)*64 + lane + 32];
        }
        u64t ya[2][4];
#pragma unroll
        for (int p = 0; p < 4; p++) { ya[0][p] = dup2(b2l0); ya[1][p] = dup2(b2l1); }
#pragma unroll 2
        for (int j = 0; j < 16; j++) {
            float4 w0 = W2T4[lane*WPAD4 + j];
            float4 w1 = W2T4[(lane+32)*WPAD4 + j];
#pragma unroll
            for (int e = 0; e < 4; e++) {
                ulonglong2 aA = *(const ulonglong2*)(ACT + (4*j+e)*TB);
                ulonglong2 aB = *(const ulonglong2*)(ACT + (4*j+e)*TB + 4);
                acc4(dup2(((const float*)&w0)[e]), aA, aB, ya[0]);
                acc4(dup2(((const float*)&w1)[e]), aA, aB, ya[1]);
            }
        }
        float yy0[TB], yy1[TB];
#pragma unroll
        for (int p = 0; p < 4; p++) {
            up2(ya[0][p], yy0[2*p], yy0[2*p+1]);
            up2(ya[1][p], yy1[2*p], yy1[2*p+1]);
        }
#pragma unroll
        for (int t = 0; t < TB; t++) { yy0[t] += v0t[t]; yy1[t] += v1t[t]; }

        // LN2 -> ACT
        float yn0[TB], yn1[TB];
#pragma unroll
        for (int t = 0; t < TB; t++) {
            float mu  = wsum(yy0[t] + yy1[t]) * inv64;
            float d0 = yy0[t] - mu, d1 = yy1[t] - mu;
            float var = wsum(d0*d0 + d1*d1) * inv64;
            float inv = rsqrtf(var + 1e-5f);
            yn0[t] = d0*inv*g2l0 + be2l0;
            yn1[t] = d1*inv*g2l1 + be2l1;
        }
        __syncwarp();
        *(float4*)(ACT + lane*TB)        = make_float4(yn0[0],yn0[1],yn0[2],yn0[3]);
        *(float4*)(ACT + lane*TB + 4)    = make_float4(yn0[4],yn0[5],yn0[6],yn0[7]);
        *(float4*)(ACT + (lane+32)*TB)   = make_float4(yn1[0],yn1[1],yn1[2],yn1[3]);
        *(float4*)(ACT + (lane+32)*TB+4) = make_float4(yn1[4],yn1[5],yn1[6],yn1[7]);
        __syncwarp();

        // m1 + GELU -> ACT
        u64t za[2][4];
#pragma unroll
        for (int p = 0; p < 4; p++) { za[0][p] = dup2(bm1l0); za[1][p] = dup2(bm1l1); }
#pragma unroll 2
        for (int j = 0; j < 16; j++) {
            float4 w0 = WM1T4[lane*WPAD4 + j];
            float4 w1 = WM1T4[(lane+32)*WPAD4 + j];
#pragma unroll
            for (int e = 0; e < 4; e++) {
                ulonglong2 aA = *(const ulonglong2*)(ACT + (4*j+e)*TB);
                ulonglong2 aB = *(const ulonglong2*)(ACT + (4*j+e)*TB + 4);
                acc4(dup2(((const float*)&w0)[e]), aA, aB, za[0]);
                acc4(dup2(((const float*)&w1)[e]), aA, aB, za[1]);
            }
        }
        float ge0[TB], ge1[TB];
#pragma unroll
        for (int p = 0; p < 4; p++) {
            up2(za[0][p], ge0[2*p], ge0[2*p+1]);
            up2(za[1][p], ge1[2*p], ge1[2*p+1]);
        }
#pragma unroll
        for (int t = 0; t < TB; t++) {
            ge0[t] = 0.5f*ge0[t]*(1.0f + erff(ge0[t]*0.70710678118654752f));
            ge1[t] = 0.5f*ge1[t]*(1.0f + erff(ge1[t]*0.70710678118654752f));
        }
        __syncwarp();
        *(float4*)(ACT + lane*TB)        = make_float4(ge0[0],ge0[1],ge0[2],ge0[3]);
        *(float4*)(ACT + lane*TB + 4)    = make_float4(ge0[4],ge0[5],ge0[6],ge0[7]);
        *(float4*)(ACT + (lane+32)*TB)   = make_float4(ge1[0],ge1[1],ge1[2],ge1[3]);
        *(float4*)(ACT + (lane+32)*TB+4) = make_float4(ge1[4],ge1[5],ge1[6],ge1[7]);
        __syncwarp();

        // m2 + residual -> out
        u64t oa[2][4];
#pragma unroll
        for (int p = 0; p < 4; p++) { oa[0][p] = dup2(bm2l0); oa[1][p] = dup2(bm2l1); }
#pragma unroll 2
        for (int j = 0; j < 16; j++) {
            float4 w0 = WM2T4[lane*WPAD4 + j];
            float4 w1 = WM2T4[(lane+32)*WPAD4 + j];
#pragma unroll
            for (int e = 0; e < 4; e++) {
                ulonglong2 aA = *(const ulonglong2*)(ACT + (4*j+e)*TB);
                ulonglong2 aB = *(const ulonglong2*)(ACT + (4*j+e)*TB + 4);
                acc4(dup2(((const float*)&w0)[e]), aA, aB, oa[0]);
                acc4(dup2(((const float*)&w1)[e]), aA, aB, oa[1]);
            }
        }
        float o0[TB], o1[TB];
#pragma unroll
        for (int p = 0; p < 4; p++) {
            up2(oa[0][p], o0[2*p], o0[2*p+1]);
            up2(oa[1][p], o1[2*p], o1[2*p+1]);
        }
#pragma unroll
        for (int t = 0; t < TB; t++) {
            out[(tok0 + t)*64 + lane]      = yy0[t] + o0[t];
            out[(tok0 + t)*64 + lane + 32] = yy1[t] + o1[t];
        }
        __syncwarp();
    }
}

// ===================== launch =====================
extern "C" void kernel_launch(void* const* d_in, const int* in_sizes, int n_in,
                              void* d_out, int out_size)
{
    const float* x   = (const float*)d_in[0];
    const float* W1  = (const float*)d_in[1];
    const float* b1  = (const float*)d_in[2];
    const float* Wk  = (const float*)d_in[3];
    const float* bk  = (const float*)d_in[4];
    const float* W2  = (const float*)d_in[5];
    const float* b2  = (const float*)d_in[6];
    const float* g1  = (const float*)d_in[7];
    const float* be1 = (const float*)d_in[8];
    const float* g2  = (const float*)d_in[9];
    const float* be2 = (const float*)d_in[10];
    const float* Wm1 = (const float*)d_in[11];
    const float* bm1 = (const float*)d_in[12];
    const float* Wm2 = (const float*)d_in[13];
    const float* bm2 = (const float*)d_in[14];
    const float* wrf = (const float*)d_in[15];
    float* out = (float*)d_out;

    cudaFuncSetAttribute(kernelA, cudaFuncAttributeMaxDynamicSharedMemorySize, A_SMEM_BYTES);
    cudaFuncSetAttribute(kernelC, cudaFuncAttributeMaxDynamicSharedMemorySize, C_SMEM_BYTES);

    kernelA<<<148, 512, A_SMEM_BYTES>>>(x, W1, b1, Wk, bk, g1, be1, wrf);
    kernelZero<<<(BATCH*DIM*MF + 255)/256, 256>>>();
    kernelB<<<dim3(8, BATCH), 256>>>();
    kernelC<<<dim3(14, BATCH), 512, C_SMEM_BYTES>>>(W2, b2, g2, be2, Wm1, bm1, Wm2, bm2, out);
}

// round 11
// speedup vs baseline: 4.4843x; 1.0005x over previous
#include <cuda_runtime.h>
#include <math.h>

#define BATCH  64
#define TSEQ   3136
#define NTOK   (BATCH*TSEQ)   // 200704
#define INDIM  147
#define DIM    64
#define MF     32
#define TB     8              // tokens per warp
#define NW     16             // warps per block (512 threads)

#define WPAD   68             // 17 float4, odd -> conflict-free
#define WPAD4  17
#define KPAD   36             // 9 float4
#define KPAD4  9

// -------- scratch --------
__device__ float d_v [NTOK*DIM];
__device__ float d_kp[NTOK*MF];
__device__ float d_qp[NTOK*MF];
__device__ float d_kpsum[BATCH*MF];
__device__ float d_kptv [BATCH*DIM*MF];

typedef unsigned long long u64t;

__device__ __forceinline__ float wsum(float v) {
#pragma unroll
    for (int o = 16; o; o >>= 1) v += __shfl_xor_sync(0xffffffffu, v, o);
    return v;
}
__device__ __forceinline__ u64t dup2(float a) {
    u64t r; asm("mov.b64 %0, {%1, %1};" : "=l"(r) : "f"(a)); return r;
}
__device__ __forceinline__ void up2(u64t v, float& a, float& b) {
    asm("mov.b64 {%0, %1}, %2;" : "=f"(a), "=f"(b) : "l"(v));
}
__device__ __forceinline__ u64t ffma2(u64t a, u64t b, u64t c) {
    u64t r; asm("fma.rn.f32x2 %0, %1, %2, %3;" : "=l"(r) : "l"(a), "l"(b), "l"(c));
    return r;
}
__device__ __forceinline__ void acc4(u64t w, ulonglong2 aA, ulonglong2 aB, u64t* acc) {
    acc[0] = ffma2(w, aA.x, acc[0]); acc[1] = ffma2(w, aA.y, acc[1]);
    acc[2] = ffma2(w, aB.x, acc[2]); acc[3] = ffma2(w, aB.y, acc[3]);
}

// ===================== Kernel A =====================
// smem floats: W1T[64][148] @0, WkT[192][68], WT[32][68],
//              SXT[NW][148*8] ([i][t], stride 8), ACT[NW][64*8] ([i][t])
#define A_W1   0
#define A_WK   9472
#define A_WT   (A_WK + 192*WPAD)
#define A_SX   (A_WT + 32*WPAD)
#define A_ACT  (A_SX + NW*148*TB)
#define A_SMEM_BYTES ((A_ACT + NW*DIM*TB)*4)

__global__ void __launch_bounds__(512) kernelA(
    const float* __restrict__ x,  const float* __restrict__ W1, const float* __restrict__ b1,
    const float* __restrict__ Wk, const float* __restrict__ bk,
    const float* __restrict__ g1, const float* __restrict__ be1,
    const float* __restrict__ wrf)
{
    extern __shared__ float sm[];
    const int tid = threadIdx.x, lane = tid & 31, warp = tid >> 5;

    for (int idx = tid; idx < 64*148; idx += 512) {
        int c = idx / 148, i = idx - c*148;
        sm[A_W1 + c*148 + i] = (i < INDIM) ? W1[i*64 + c] : 0.f;
    }
    for (int idx = tid; idx < 192*64; idx += 512) {
        int c = idx >> 6, i = idx & 63;
        sm[A_WK + c*WPAD + i] = Wk[i*192 + c];
    }
    for (int idx = tid; idx < MF*DIM; idx += 512) {
        int m = idx >> 6, d = idx & 63;
        sm[A_WT + m*WPAD + d] = wrf[m*64 + d];
    }
    __syncthreads();

    const float b1l0 = b1[lane], b1l1 = b1[lane+32];
    float bkl[6];
#pragma unroll
    for (int c = 0; c < 6; c++) bkl[c] = bk[((c&1)?32:0) + (c>>1)*64 + lane];
    const float g1l0 = g1[lane], g1l1 = g1[lane+32];
    const float be1l0 = be1[lane], be1l1 = be1[lane+32];

    float* SXT = sm + A_SX  + warp*148*TB;   // [i][t], stride 8
    float* ACT = sm + A_ACT + warp*DIM*TB;   // [i][t], stride 8
    const float4* W1T4 = (const float4*)(sm + A_W1);
    const float4* WKT4 = (const float4*)(sm + A_WK);
    const float4* WT4  = (const float4*)(sm + A_WT);
    const float inv64 = 1.0f/64.0f;
    const float rsM   = 0.17677669529663689f;

    const int tl = lane >> 2;    // token 0..7 owned by this lane for loads
    const int il = lane & 3;     // i4 sub-index

    for (long long base = (long long)(blockIdx.x*NW + warp)*TB; base < NTOK;
         base += (long long)gridDim.x*NW*TB) {
        // ---- load x tile directly transposed: SXT[i][t] ----
        {
            const float* xr = x + (base + tl)*INDIM;
#pragma unroll
            for (int it = 0; it < 10; it++) {
                int i4 = il + 4*it;
                if (i4 <= 36) {
                    int i0 = 4*i4;
                    float v0 = xr[i0];
                    float v1 = xr[i0+1];
                    float v2 = xr[i0+2];
                    float v3 = (i0+3 < INDIM) ? xr[i0+3] : 0.f;
                    SXT[(i0  )*TB + tl] = v0;
                    SXT[(i0+1)*TB + tl] = v1;
                    SXT[(i0+2)*TB + tl] = v2;
                    SXT[(i0+3)*TB + tl] = v3;
                }
            }
        }
        __syncwarp();

        // ---- h = x @ W1 + b1 (f32x2) ----
        u64t ha[2][4];
#pragma unroll
        for (int p = 0; p < 4; p++) { ha[0][p] = dup2(b1l0); ha[1][p] = dup2(b1l1); }
#pragma unroll 1
        for (int j = 0; j < 37; j++) {
            float4 w0 = W1T4[lane*37 + j];
            float4 w1 = W1T4[(lane+32)*37 + j];
#pragma unroll
            for (int e = 0; e < 4; e++) {
                ulonglong2 aA = *(const ulonglong2*)(SXT + (4*j+e)*TB);
                ulonglong2 aB = *(const ulonglong2*)(SXT + (4*j+e)*TB + 4);
                acc4(dup2(((const float*)&w0)[e]), aA, aB, ha[0]);
                acc4(dup2(((const float*)&w1)[e]), aA, aB, ha[1]);
            }
        }
        float hh0[TB], hh1[TB];
#pragma unroll
        for (int p = 0; p < 4; p++) {
            up2(ha[0][p], hh0[2*p], hh0[2*p+1]);
            up2(ha[1][p], hh1[2*p], hh1[2*p+1]);
        }

        // ---- LN1 -> ACT [i][t] ----
        float hn0[TB], hn1[TB];
#pragma unroll
        for (int t = 0; t < TB; t++) {
            float mu  = wsum(hh0[t] + hh1[t]) * inv64;
            float d0 = hh0[t] - mu, d1 = hh1[t] - mu;
            float var = wsum(d0*d0 + d1*d1) * inv64;
            float inv = rsqrtf(var + 1e-5f);
            hn0[t] = d0*inv*g1l0 + be1l0;
            hn1[t] = d1*inv*g1l1 + be1l1;
        }
        __syncwarp();
        *(float4*)(ACT + lane*TB)        = make_float4(hn0[0],hn0[1],hn0[2],hn0[3]);
        *(float4*)(ACT + lane*TB + 4)    = make_float4(hn0[4],hn0[5],hn0[6],hn0[7]);
        *(float4*)(ACT + (lane+32)*TB)   = make_float4(hn1[0],hn1[1],hn1[2],hn1[3]);
        *(float4*)(ACT + (lane+32)*TB+4) = make_float4(hn1[4],hn1[5],hn1[6],hn1[7]);
        __syncwarp();

        // ---- kqv (f32x2, token pairs) ----
        u64t ka[2][4], qa[2][4], va[2][4];
#pragma unroll
        for (int p = 0; p < 4; p++) {
            ka[0][p]=dup2(bkl[0]); ka[1][p]=dup2(bkl[1]);
            qa[0][p]=dup2(bkl[2]); qa[1][p]=dup2(bkl[3]);
            va[0][p]=dup2(bkl[4]); va[1][p]=dup2(bkl[5]);
        }
#pragma unroll 1
        for (int j = 0; j < 16; j++) {
            float4 wk0 = WKT4[(lane     )*WPAD4 + j];
            float4 wk1 = WKT4[(lane + 32)*WPAD4 + j];
            float4 wq0 = WKT4[(lane + 64)*WPAD4 + j];
            float4 wq1 = WKT4[(lane + 96)*WPAD4 + j];
            float4 wv0 = WKT4[(lane +128)*WPAD4 + j];
            float4 wv1 = WKT4[(lane +160)*WPAD4 + j];
#pragma unroll
            for (int e = 0; e < 4; e++) {
                ulonglong2 aA = *(const ulonglong2*)(ACT + (4*j+e)*TB);
                ulonglong2 aB = *(const ulonglong2*)(ACT + (4*j+e)*TB + 4);
                acc4(dup2(((const float*)&wk0)[e]), aA, aB, ka[0]);
                acc4(dup2(((const float*)&wk1)[e]), aA, aB, ka[1]);
                acc4(dup2(((const float*)&wq0)[e]), aA, aB, qa[0]);
                acc4(dup2(((const float*)&wq1)[e]), aA, aB, qa[1]);
                acc4(dup2(((const float*)&wv0)[e]), aA, aB, va[0]);
                acc4(dup2(((const float*)&wv1)[e]), aA, aB, va[1]);
            }
        }

        // ---- kp ----
        float kk0[TB], kk1[TB];
#pragma unroll
        for (int p = 0; p < 4; p++) {
            up2(ka[0][p], kk0[2*p], kk0[2*p+1]);
            up2(ka[1][p], kk1[2*p], kk1[2*p+1]);
        }
        float xdk[TB];
#pragma unroll
        for (int t = 0; t < TB; t++)
            xdk[t] = 0.5f * wsum(kk0[t]*kk0[t] + kk1[t]*kk1[t]);
        __syncwarp();
        *(float4*)(ACT + lane*TB)        = make_float4(kk0[0],kk0[1],kk0[2],kk0[3]);
        *(float4*)(ACT + lane*TB + 4)    = make_float4(kk0[4],kk0[5],kk0[6],kk0[7]);
        *(float4*)(ACT + (lane+32)*TB)   = make_float4(kk1[0],kk1[1],kk1[2],kk1[3]);
        *(float4*)(ACT + (lane+32)*TB+4) = make_float4(kk1[4],kk1[5],kk1[6],kk1[7]);
        __syncwarp();
        {
            u64t pa[4] = {0ull,0ull,0ull,0ull};
#pragma unroll 2
            for (int j = 0; j < 16; j++) {
                float4 w = WT4[lane*WPAD4 + j];
#pragma unroll
                for (int e = 0; e < 4; e++) {
                    ulonglong2 aA = *(const ulonglong2*)(ACT + (4*j+e)*TB);
                    ulonglong2 aB = *(const ulonglong2*)(ACT + (4*j+e)*TB + 4);
                    acc4(dup2(((const float*)&w)[e]), aA, aB, pa);
                }
            }
            float pk[TB];
#pragma unroll
            for (int p = 0; p < 4; p++) up2(pa[p], pk[2*p], pk[2*p+1]);
#pragma unroll
            for (int t = 0; t < TB; t++)
                d_kp[(base + t)*MF + lane] = __expf(pk[t] - xdk[t]) * rsM;
        }

        // ---- qp ----
        float qq0[TB], qq1[TB];
#pragma unroll
        for (int p = 0; p < 4; p++) {
            up2(qa[0][p], qq0[2*p], qq0[2*p+1]);
            up2(qa[1][p], qq1[2*p], qq1[2*p+1]);
        }
        float xdq[TB];
#pragma unroll
        for (int t = 0; t < TB; t++)
            xdq[t] = 0.5f * wsum(qq0[t]*qq0[t] + qq1[t]*qq1[t]);
        __syncwarp();
        *(float4*)(ACT + lane*TB)        = make_float4(qq0[0],qq0[1],qq0[2],qq0[3]);
        *(float4*)(ACT + lane*TB + 4)    = make_float4(qq0[4],qq0[5],qq0[6],qq0[7]);
        *(float4*)(ACT + (lane+32)*TB)   = make_float4(qq1[0],qq1[1],qq1[2],qq1[3]);
        *(float4*)(ACT + (lane+32)*TB+4) = make_float4(qq1[4],qq1[5],qq1[6],qq1[7]);
        __syncwarp();
        {
            u64t pa[4] = {0ull,0ull,0ull,0ull};
#pragma unroll 2
            for (int j = 0; j < 16; j++) {
                float4 w = WT4[lane*WPAD4 + j];
#pragma unroll
                for (int e = 0; e < 4; e++) {
                    ulonglong2 aA = *(const ulonglong2*)(ACT + (4*j+e)*TB);
                    ulonglong2 aB = *(const ulonglong2*)(ACT + (4*j+e)*TB + 4);
                    acc4(dup2(((const float*)&w)[e]), aA, aB, pa);
                }
            }
            float pq[TB];
#pragma unroll
            for (int p = 0; p < 4; p++) up2(pa[p], pq[2*p], pq[2*p+1]);
#pragma unroll
            for (int t = 0; t < TB; t++)
                d_qp[(base + t)*MF + lane] = __expf(pq[t] - xdq[t]) * rsM;
        }

        // ---- v ----
        float v0t[TB], v1t[TB];
#pragma unroll
        for (int p = 0; p < 4; p++) {
            up2(va[0][p], v0t[2*p], v0t[2*p+1]);
            up2(va[1][p], v1t[2*p], v1t[2*p+1]);
        }
#pragma unroll
        for (int t = 0; t < TB; t++) {
            d_v[(base + t)*64 + lane]      = v0t[t];
            d_v[(base + t)*64 + lane + 32] = v1t[t];
        }
        __syncwarp();
    }
}

// ===================== zero =====================
__global__ void kernelZero() {
    int i = blockIdx.x*blockDim.x + threadIdx.x;
    if (i < BATCH*MF)     d_kpsum[i] = 0.f;
    if (i < BATCH*DIM*MF) d_kptv[i]  = 0.f;
}

// ===================== Kernel B =====================
#define B_TILE 8
__global__ void __launch_bounds__(256) kernelB()
{
    __shared__ float sv [B_TILE*64];
    __shared__ float skp[B_TILE*32];
    const int tid = threadIdx.x;
    const int b   = blockIdx.y;
    const int m   = tid & 31, dg = tid >> 5;

    float acc[8];
#pragma unroll
    for (int j = 0; j < 8; j++) acc[j] = 0.f;
    float ks = 0.f;

    const int t0 = blockIdx.x * (TSEQ/8);
    const int t1 = t0 + (TSEQ/8);
    for (int base = t0; base < t1; base += B_TILE) {
        __syncthreads();
        {
            const float4* src = (const float4*)(d_v + ((long long)(b*TSEQ + base))*64);
            float4* dst = (float4*)sv;
            if (tid < B_TILE*16) dst[tid] = src[tid];
            const float4* srck = (const float4*)(d_kp + ((long long)(b*TSEQ + base))*32);
            float4* dstk = (float4*)skp;
            if (tid < B_TILE*8) dstk[tid] = srck[tid];
        }
        __syncthreads();
#pragma unroll
        for (int tt = 0; tt < B_TILE; tt++) {
            float kpm = skp[tt*32 + m];
#pragma unroll
            for (int j = 0; j < 8; j++)
                acc[j] = fmaf(kpm, sv[tt*64 + dg*8 + j], acc[j]);
            if (dg == 0) ks += kpm;
        }
    }
#pragma unroll
    for (int j = 0; j < 8; j++)
        atomicAdd(&d_kptv[b*2048 + (dg*8 + j)*32 + m], acc[j]);
    if (dg == 0) atomicAdd(&d_kpsum[b*32 + m], ks);
}

// ===================== Kernel C =====================
#define C_W2    0
#define C_WM1   (C_W2 + 64*WPAD)
#define C_WM2   (C_WM1 + 64*WPAD)
#define C_KPTV  (C_WM2 + 64*WPAD)
#define C_KPS   (C_KPTV + 64*KPAD)
#define C_ACT   (C_KPS + 32)
#define C_QP    (C_ACT + NW*DIM*TB)
#define C_SMEM_BYTES ((C_QP + NW*MF*TB)*4)

__global__ void __launch_bounds__(512) kernelC(
    const float* __restrict__ W2,  const float* __restrict__ b2,
    const float* __restrict__ g2,  const float* __restrict__ be2,
    const float* __restrict__ Wm1, const float* __restrict__ bm1,
    const float* __restrict__ Wm2, const float* __restrict__ bm2,
    float* __restrict__ out)
{
    extern __shared__ float sm[];
    const int tid = threadIdx.x, lane = tid & 31, warp = tid >> 5;
    const int b = blockIdx.y;

    for (int idx = tid; idx < 4096; idx += 512) {
        int c = idx >> 6, i = idx & 63;
        sm[C_W2  + c*WPAD + i] = W2 [i*64 + c];
        sm[C_WM1 + c*WPAD + i] = Wm1[i*64 + c];
        sm[C_WM2 + c*WPAD + i] = Wm2[i*64 + c];
    }
    for (int i = tid; i < 2048; i += 512) {
        int d = i >> 5, m = i & 31;
        sm[C_KPTV + d*KPAD + m] = d_kptv[b*2048 + i];
    }
    if (tid < 32) sm[C_KPS + tid] = d_kpsum[b*32 + tid];
    __syncthreads();

    const float b2l0 = b2[lane], b2l1 = b2[lane+32];
    const float g2l0 = g2[lane], g2l1 = g2[lane+32];
    const float be2l0 = be2[lane], be2l1 = be2[lane+32];
    const float bm1l0 = bm1[lane], bm1l1 = bm1[lane+32];
    const float bm2l0 = bm2[lane], bm2l1 = bm2[lane+32];
    const float kpsl = sm[C_KPS + lane];

    float* ACT = sm + C_ACT + warp*DIM*TB;
    float* QP  = sm + C_QP  + warp*MF*TB;
    const float4* W2T4  = (const float4*)(sm + C_W2);
    const float4* WM1T4 = (const float4*)(sm + C_WM1);
    const float4* WM2T4 = (const float4*)(sm + C_WM2);
    const float4* KPTV4 = (const float4*)(sm + C_KPTV);
    const float inv64 = 1.0f/64.0f;

    for (int lt = (blockIdx.x*NW + warp)*TB; lt < TSEQ; lt += gridDim.x*NW*TB) {
        const long long tok0 = (long long)b*TSEQ + lt;

        float qpv[TB], rD[TB];
#pragma unroll
        for (int t = 0; t < TB; t++) {
            qpv[t] = d_qp[(tok0 + t)*MF + lane];
            float D = wsum(qpv[t] * kpsl);
            rD[t] = 1.0f / (D + 1e-8f);
        }
        __syncwarp();
        *(float4*)(QP + lane*TB)     = make_float4(qpv[0],qpv[1],qpv[2],qpv[3]);
        *(float4*)(QP + lane*TB + 4) = make_float4(qpv[4],qpv[5],qpv[6],qpv[7]);
        __syncwarp();

        // att = qp @ kptv^T (f32x2)
        u64t aacc[2][4];
#pragma unroll
        for (int p = 0; p < 4; p++) { aacc[0][p] = 0ull; aacc[1][p] = 0ull; }
#pragma unroll 2
        for (int j = 0; j < 8; j++) {
            float4 w0 = KPTV4[lane*KPAD4 + j];
            float4 w1 = KPTV4[(lane+32)*KPAD4 + j];
#pragma unroll
            for (int e = 0; e < 4; e++) {
                ulonglong2 aA = *(const ulonglong2*)(QP + (4*j+e)*TB);
                ulonglong2 aB = *(const ulonglong2*)(QP + (4*j+e)*TB + 4);
                acc4(dup2(((const float*)&w0)[e]), aA, aB, aacc[0]);
                acc4(dup2(((const float*)&w1)[e]), aA, aB, aacc[1]);
            }
        }
        float a0[TB], a1[TB];
#pragma unroll
        for (int p = 0; p < 4; p++) {
            up2(aacc[0][p], a0[2*p], a0[2*p+1]);
            up2(aacc[1][p], a1[2*p], a1[2*p+1]);
        }
        __syncwarp();
        *(float4*)(ACT + lane*TB)        = make_float4(a0[0]*rD[0],a0[1]*rD[1],a0[2]*rD[2],a0[3]*rD[3]);
        *(float4*)(ACT + lane*TB + 4)    = make_float4(a0[4]*rD[4],a0[5]*rD[5],a0[6]*rD[6],a0[7]*rD[7]);
        *(float4*)(ACT + (lane+32)*TB)   = make_float4(a1[0]*rD[0],a1[1]*rD[1],a1[2]*rD[2],a1[3]*rD[3]);
        *(float4*)(ACT + (lane+32)*TB+4) = make_float4(a1[4]*rD[4],a1[5]*rD[5],a1[6]*rD[6],a1[7]*rD[7]);
        __syncwarp();

        // y = v + att @ W2 + b2
        float v0t[TB], v1t[TB];
#pragma unroll
        for (int t = 0; t < TB; t++) {
            v0t[t] = d_v[(tok0 + t)*64 + lane];
            v1t[t] = d_v[(tok0 + t)*64 + lane + 32];
        }
        u64t ya[2][4];
#pragma unroll
        for (int p = 0; p < 4; p++) { ya[0][p] = dup2(b2l0); ya[1][p] = dup2(b2l1); }
#pragma unroll 2
        for (int j = 0; j < 16; j++) {
            float4 w0 = W2T4[lane*WPAD4 + j];
            float4 w1 = W2T4[(lane+32)*WPAD4 + j];
#pragma unroll
            for (int e = 0; e < 4; e++) {
                ulonglong2 aA = *(const ulonglong2*)(ACT + (4*j+e)*TB);
                ulonglong2 aB = *(const ulonglong2*)(ACT + (4*j+e)*TB + 4);
                acc4(dup2(((const float*)&w0)[e]), aA, aB, ya[0]);
                acc4(dup2(((const float*)&w1)[e]), aA, aB, ya[1]);
            }
        }
        float yy0[TB], yy1[TB];
#pragma unroll
        for (int p = 0; p < 4; p++) {
            up2(ya[0][p], yy0[2*p], yy0[2*p+1]);
            up2(ya[1][p], yy1[2*p], yy1[2*p+1]);
        }
#pragma unroll
        for (int t = 0; t < TB; t++) { yy0[t] += v0t[t]; yy1[t] += v1t[t]; }

        // LN2 -> ACT
        float yn0[TB], yn1[TB];
#pragma unroll
        for (int t = 0; t < TB; t++) {
            float mu  = wsum(yy0[t] + yy1[t]) * inv64;
            float d0 = yy0[t] - mu, d1 = yy1[t] - mu;
            float var = wsum(d0*d0 + d1*d1) * inv64;
            float inv = rsqrtf(var + 1e-5f);
            yn0[t] = d0*inv*g2l0 + be2l0;
            yn1[t] = d1*inv*g2l1 + be2l1;
        }
        __syncwarp();
        *(float4*)(ACT + lane*TB)        = make_float4(yn0[0],yn0[1],yn0[2],yn0[3]);
        *(float4*)(ACT + lane*TB + 4)    = make_float4(yn0[4],yn0[5],yn0[6],yn0[7]);
        *(float4*)(ACT + (lane+32)*TB)   = make_float4(yn1[0],yn1[1],yn1[2],yn1[3]);
        *(float4*)(ACT + (lane+32)*TB+4) = make_float4(yn1[4],yn1[5],yn1[6],yn1[7]);
        __syncwarp();

        // m1 + GELU -> ACT
        u64t za[2][4];
#pragma unroll
        for (int p = 0; p < 4; p++) { za[0][p] = dup2(bm1l0); za[1][p] = dup2(bm1l1); }
#pragma unroll 2
        for (int j = 0; j < 16; j++) {
            float4 w0 = WM1T4[lane*WPAD4 + j];
            float4 w1 = WM1T4[(lane+32)*WPAD4 + j];
#pragma unroll
            for (int e = 0; e < 4; e++) {
                ulonglong2 aA = *(const ulonglong2*)(ACT + (4*j+e)*TB);
                ulonglong2 aB = *(const ulonglong2*)(ACT + (4*j+e)*TB + 4);
                acc4(dup2(((const float*)&w0)[e]), aA, aB, za[0]);
                acc4(dup2(((const float*)&w1)[e]), aA, aB, za[1]);
            }
        }
        float ge0[TB], ge1[TB];
#pragma unroll
        for (int p = 0; p < 4; p++) {
            up2(za[0][p], ge0[2*p], ge0[2*p+1]);
            up2(za[1][p], ge1[2*p], ge1[2*p+1]);
        }
#pragma unroll
        for (int t = 0; t < TB; t++) {
            ge0[t] = 0.5f*ge0[t]*(1.0f + erff(ge0[t]*0.70710678118654752f));
            ge1[t] = 0.5f*ge1[t]*(1.0f + erff(ge1[t]*0.70710678118654752f));
        }
        __syncwarp();
        *(float4*)(ACT + lane*TB)        = make_float4(ge0[0],ge0[1],ge0[2],ge0[3]);
        *(float4*)(ACT + lane*TB + 4)    = make_float4(ge0[4],ge0[5],ge0[6],ge0[7]);
        *(float4*)(ACT + (lane+32)*TB)   = make_float4(ge1[0],ge1[1],ge1[2],ge1[3]);
        *(float4*)(ACT + (lane+32)*TB+4) = make_float4(ge1[4],ge1[5],ge1[6],ge1[7]);
        __syncwarp();

        // m2 + residual -> out
        u64t oa[2][4];
#pragma unroll
        for (int p = 0; p < 4; p++) { oa[0][p] = dup2(bm2l0); oa[1][p] = dup2(bm2l1); }
#pragma unroll 2
        for (int j = 0; j < 16; j++) {
            float4 w0 = WM2T4[lane*WPAD4 + j];
            float4 w1 = WM2T4[(lane+32)*WPAD4 + j];
#pragma unroll
            for (int e = 0; e < 4; e++) {
                ulonglong2 aA = *(const ulonglong2*)(ACT + (4*j+e)*TB);
                ulonglong2 aB = *(const ulonglong2*)(ACT + (4*j+e)*TB + 4);
                acc4(dup2(((const float*)&w0)[e]), aA, aB, oa[0]);
                acc4(dup2(((const float*)&w1)[e]), aA, aB, oa[1]);
            }
        }
        float o0[TB], o1[TB];
#pragma unroll
        for (int p = 0; p < 4; p++) {
            up2(oa[0][p], o0[2*p], o0[2*p+1]);
            up2(oa[1][p], o1[2*p], o1[2*p+1]);
        }
#pragma unroll
        for (int t = 0; t < TB; t++) {
            out[(tok0 + t)*64 + lane]      = yy0[t] + o0[t];
            out[(tok0 + t)*64 + lane + 32] = yy1[t] + o1[t];
        }
        __syncwarp();
    }
}

// ===================== launch =====================
extern "C" void kernel_launch(void* const* d_in, const int* in_sizes, int n_in,
                              void* d_out, int out_size)
{
    const float* x   = (const float*)d_in[0];
    const float* W1  = (const float*)d_in[1];
    const float* b1  = (const float*)d_in[2];
    const float* Wk  = (const float*)d_in[3];
    const float* bk  = (const float*)d_in[4];
    const float* W2  = (const float*)d_in[5];
    const float* b2  = (const float*)d_in[6];
    const float* g1  = (const float*)d_in[7];
    const float* be1 = (const float*)d_in[8];
    const float* g2  = (const float*)d_in[9];
    const float* be2 = (const float*)d_in[10];
    const float* Wm1 = (const float*)d_in[11];
    const float* bm1 = (const float*)d_in[12];
    const float* Wm2 = (const float*)d_in[13];
    const float* bm2 = (const float*)d_in[14];
    const float* wrf = (const float*)d_in[15];
    float* out = (float*)d_out;

    cudaFuncSetAttribute(kernelA, cudaFuncAttributeMaxDynamicSharedMemorySize, A_SMEM_BYTES);
    cudaFuncSetAttribute(kernelC, cudaFuncAttributeMaxDynamicSharedMemorySize, C_SMEM_BYTES);

    kernelA<<<148, 512, A_SMEM_BYTES>>>(x, W1, b1, Wk, bk, g1, be1, wrf);
    kernelZero<<<(BATCH*DIM*MF + 255)/256, 256>>>();
    kernelB<<<dim3(8, BATCH), 256>>>();
    kernelC<<<dim3(14, BATCH), 512, C_SMEM_BYTES>>>(W2, b2, g2, be2, Wm1, bm1, Wm2, bm2, out);
}

// round 13
// speedup vs baseline: 5.0485x; 1.1258x over previous
#include <cuda_runtime.h>
#include <math.h>

#define BATCH  64
#define TSEQ   3136
#define NTOK   (BATCH*TSEQ)
#define INDIM  147
#define DIM    64
#define MF     32
#define TB     8
#define NW     16
#define NTILE  196            // TSEQ/16

#define WPAD   68
#define WPAD4  17
#define CW     68             // kernelC weight row stride (floats)

__device__ float d_v [NTOK*DIM];      // [token][64]
__device__ float d_kp[NTOK*MF];       // [token][32]
__device__ float d_qp[NTOK*MF];       // tiled [tile][m][16]
__device__ float d_kpsum[BATCH*MF];
__device__ float d_kptv [BATCH*DIM*MF];

typedef unsigned long long u64t;

__device__ __forceinline__ float wsum(float v) {
#pragma unroll
    for (int o = 16; o; o >>= 1) v += __shfl_xor_sync(0xffffffffu, v, o);
    return v;
}
__device__ __forceinline__ u64t dup2(float a) {
    u64t r; asm("mov.b64 %0, {%1, %1};" : "=l"(r) : "f"(a)); return r;
}
__device__ __forceinline__ u64t pack2(float lo, float hi) {
    u64t r; asm("mov.b64 %0, {%1, %2};" : "=l"(r) : "f"(lo), "f"(hi)); return r;
}
__device__ __forceinline__ void up2(u64t v, float& a, float& b) {
    asm("mov.b64 {%0, %1}, %2;" : "=f"(a), "=f"(b) : "l"(v));
}
__device__ __forceinline__ u64t ffma2(u64t a, u64t b, u64t c) {
    u64t r; asm("fma.rn.f32x2 %0, %1, %2, %3;" : "=l"(r) : "l"(a), "l"(b), "l"(c));
    return r;
}
__device__ __forceinline__ u64t mul2(u64t a, u64t b) {
    u64t r; asm("mul.rn.f32x2 %0, %1, %2;" : "=l"(r) : "l"(a), "l"(b)); return r;
}
__device__ __forceinline__ u64t add2(u64t a, u64t b) {
    u64t r; asm("add.rn.f32x2 %0, %1, %2;" : "=l"(r) : "l"(a), "l"(b)); return r;
}
__device__ __forceinline__ u64t shflx(u64t v, int m) {
    return __shfl_xor_sync(0xffffffffu, v, m);
}
__device__ __forceinline__ void acc4(u64t w, ulonglong2 aA, ulonglong2 aB, u64t* acc) {
    acc[0] = ffma2(w, aA.x, acc[0]); acc[1] = ffma2(w, aA.y, acc[1]);
    acc[2] = ffma2(w, aB.x, acc[2]); acc[3] = ffma2(w, aB.y, acc[3]);
}
__device__ __forceinline__ float gelu(float z) {
    return 0.5f*z*(1.0f + erff(z*0.70710678118654752f));
}

// ===================== Kernel A =====================
#define A_W1   0
#define A_WK   9472
#define A_WT   (A_WK + 192*WPAD)
#define A_SX   (A_WT + 32*WPAD)
#define A_ACT  (A_SX + NW*148*TB)
#define A_SMEM_BYTES ((A_ACT + NW*DIM*TB)*4)

__global__ void __launch_bounds__(512) kernelA(
    const float* __restrict__ x,  const float* __restrict__ W1, const float* __restrict__ b1,
    const float* __restrict__ Wk, const float* __restrict__ bk,
    const float* __restrict__ g1, const float* __restrict__ be1,
    const float* __restrict__ wrf)
{
    extern __shared__ float sm[];
    const int tid = threadIdx.x, lane = tid & 31, warp = tid >> 5;

    for (int idx = tid; idx < 64*148; idx += 512) {
        int c = idx / 148, i = idx - c*148;
        sm[A_W1 + c*148 + i] = (i < INDIM) ? W1[i*64 + c] : 0.f;
    }
    for (int idx = tid; idx < 192*64; idx += 512) {
        int c = idx >> 6, i = idx & 63;
        sm[A_WK + c*WPAD + i] = Wk[i*192 + c];
    }
    for (int idx = tid; idx < MF*DIM; idx += 512) {
        int m = idx >> 6, d = idx & 63;
        sm[A_WT + m*WPAD + d] = wrf[m*64 + d];
    }
    __syncthreads();

    const float b1l0 = b1[lane], b1l1 = b1[lane+32];
    float bkl[6];
#pragma unroll
    for (int c = 0; c < 6; c++) bkl[c] = bk[((c&1)?32:0) + (c>>1)*64 + lane];
    const float g1l0 = g1[lane], g1l1 = g1[lane+32];
    const float be1l0 = be1[lane], be1l1 = be1[lane+32];

    float* SXT = sm + A_SX  + warp*148*TB;
    float* ACT = sm + A_ACT + warp*DIM*TB;
    const float4* W1T4 = (const float4*)(sm + A_W1);
    const float4* WKT4 = (const float4*)(sm + A_WK);
    const float4* WT4  = (const float4*)(sm + A_WT);
    const float inv64 = 1.0f/64.0f;
    const float rsM   = 0.17677669529663689f;

    const int tl = lane >> 2, il = lane & 3;

    for (long long base = (long long)(blockIdx.x*NW + warp)*TB; base < NTOK;
         base += (long long)gridDim.x*NW*TB) {
        {
            const float* xr = x + (base + tl)*INDIM;
#pragma unroll
            for (int it = 0; it < 10; it++) {
                int i4 = il + 4*it;
                if (i4 <= 36) {
                    int i0 = 4*i4;
                    float v0 = xr[i0], v1 = xr[i0+1], v2 = xr[i0+2];
                    float v3 = (i0+3 < INDIM) ? xr[i0+3] : 0.f;
                    SXT[(i0  )*TB + tl] = v0; SXT[(i0+1)*TB + tl] = v1;
                    SXT[(i0+2)*TB + tl] = v2; SXT[(i0+3)*TB + tl] = v3;
                }
            }
        }
        __syncwarp();

        u64t ha[2][4];
#pragma unroll
        for (int p = 0; p < 4; p++) { ha[0][p] = dup2(b1l0); ha[1][p] = dup2(b1l1); }
#pragma unroll 1
        for (int j = 0; j < 37; j++) {
            float4 w0 = W1T4[lane*37 + j];
            float4 w1 = W1T4[(lane+32)*37 + j];
#pragma unroll
            for (int e = 0; e < 4; e++) {
                ulonglong2 aA = *(const ulonglong2*)(SXT + (4*j+e)*TB);
                ulonglong2 aB = *(const ulonglong2*)(SXT + (4*j+e)*TB + 4);
                acc4(dup2(((const float*)&w0)[e]), aA, aB, ha[0]);
                acc4(dup2(((const float*)&w1)[e]), aA, aB, ha[1]);
            }
        }
        float hh0[TB], hh1[TB];
#pragma unroll
        for (int p = 0; p < 4; p++) {
            up2(ha[0][p], hh0[2*p], hh0[2*p+1]);
            up2(ha[1][p], hh1[2*p], hh1[2*p+1]);
        }

        float hn0[TB], hn1[TB];
#pragma unroll
        for (int t = 0; t < TB; t++) {
            float mu  = wsum(hh0[t] + hh1[t]) * inv64;
            float d0 = hh0[t] - mu, d1 = hh1[t] - mu;
            float var = wsum(d0*d0 + d1*d1) * inv64;
            float inv = rsqrtf(var + 1e-5f);
            hn0[t] = d0*inv*g1l0 + be1l0;
            hn1[t] = d1*inv*g1l1 + be1l1;
        }
        __syncwarp();
        *(float4*)(ACT + lane*TB)        = make_float4(hn0[0],hn0[1],hn0[2],hn0[3]);
        *(float4*)(ACT + lane*TB + 4)    = make_float4(hn0[4],hn0[5],hn0[6],hn0[7]);
        *(float4*)(ACT + (lane+32)*TB)   = make_float4(hn1[0],hn1[1],hn1[2],hn1[3]);
        *(float4*)(ACT + (lane+32)*TB+4) = make_float4(hn1[4],hn1[5],hn1[6],hn1[7]);
        __syncwarp();

        u64t ka[2][4], qa[2][4], va[2][4];
#pragma unroll
        for (int p = 0; p < 4; p++) {
            ka[0][p]=dup2(bkl[0]); ka[1][p]=dup2(bkl[1]);
            qa[0][p]=dup2(bkl[2]); qa[1][p]=dup2(bkl[3]);
            va[0][p]=dup2(bkl[4]); va[1][p]=dup2(bkl[5]);
        }
#pragma unroll 1
        for (int j = 0; j < 16; j++) {
            float4 wk0 = WKT4[(lane     )*WPAD4 + j];
            float4 wk1 = WKT4[(lane + 32)*WPAD4 + j];
            float4 wq0 = WKT4[(lane + 64)*WPAD4 + j];
            float4 wq1 = WKT4[(lane + 96)*WPAD4 + j];
            float4 wv0 = WKT4[(lane +128)*WPAD4 + j];
            float4 wv1 = WKT4[(lane +160)*WPAD4 + j];
#pragma unroll
            for (int e = 0; e < 4; e++) {
                ulonglong2 aA = *(const ulonglong2*)(ACT + (4*j+e)*TB);
                ulonglong2 aB = *(const ulonglong2*)(ACT + (4*j+e)*TB + 4);
                acc4(dup2(((const float*)&wk0)[e]), aA, aB, ka[0]);
                acc4(dup2(((const float*)&wk1)[e]), aA, aB, ka[1]);
                acc4(dup2(((const float*)&wq0)[e]), aA, aB, qa[0]);
                acc4(dup2(((const float*)&wq1)[e]), aA, aB, qa[1]);
                acc4(dup2(((const float*)&wv0)[e]), aA, aB, va[0]);
                acc4(dup2(((const float*)&wv1)[e]), aA, aB, va[1]);
            }
        }

        // ---- kp ----
        float kk0[TB], kk1[TB];
#pragma unroll
        for (int p = 0; p < 4; p++) {
            up2(ka[0][p], kk0[2*p], kk0[2*p+1]);
            up2(ka[1][p], kk1[2*p], kk1[2*p+1]);
        }
        float xdk[TB];
#pragma unroll
        for (int t = 0; t < TB; t++)
            xdk[t] = 0.5f * wsum(kk0[t]*kk0[t] + kk1[t]*kk1[t]);
        __syncwarp();
        *(float4*)(ACT + lane*TB)        = make_float4(kk0[0],kk0[1],kk0[2],kk0[3]);
        *(float4*)(ACT + lane*TB + 4)    = make_float4(kk0[4],kk0[5],kk0[6],kk0[7]);
        *(float4*)(ACT + (lane+32)*TB)   = make_float4(kk1[0],kk1[1],kk1[2],kk1[3]);
        *(float4*)(ACT + (lane+32)*TB+4) = make_float4(kk1[4],kk1[5],kk1[6],kk1[7]);
        __syncwarp();
        {
            u64t pa[4] = {0ull,0ull,0ull,0ull};
#pragma unroll 2
            for (int j = 0; j < 16; j++) {
                float4 w = WT4[lane*WPAD4 + j];
#pragma unroll
                for (int e = 0; e < 4; e++) {
                    ulonglong2 aA = *(const ulonglong2*)(ACT + (4*j+e)*TB);
                    ulonglong2 aB = *(const ulonglong2*)(ACT + (4*j+e)*TB + 4);
                    acc4(dup2(((const float*)&w)[e]), aA, aB, pa);
                }
            }
            float pk[TB];
#pragma unroll
            for (int p = 0; p < 4; p++) up2(pa[p], pk[2*p], pk[2*p+1]);
#pragma unroll
            for (int t = 0; t < TB; t++)
                d_kp[(base + t)*MF + lane] = __expf(pk[t] - xdk[t]) * rsM;
        }

        // ---- qp (tiled store [tile][m][16]) ----
        float qq0[TB], qq1[TB];
#pragma unroll
        for (int p = 0; p < 4; p++) {
            up2(qa[0][p], qq0[2*p], qq0[2*p+1]);
            up2(qa[1][p], qq1[2*p], qq1[2*p+1]);
        }
        float xdq[TB];
#pragma unroll
        for (int t = 0; t < TB; t++)
            xdq[t] = 0.5f * wsum(qq0[t]*qq0[t] + qq1[t]*qq1[t]);
        __syncwarp();
        *(float4*)(ACT + lane*TB)        = make_float4(qq0[0],qq0[1],qq0[2],qq0[3]);
        *(float4*)(ACT + lane*TB + 4)    = make_float4(qq0[4],qq0[5],qq0[6],qq0[7]);
        *(float4*)(ACT + (lane+32)*TB)   = make_float4(qq1[0],qq1[1],qq1[2],qq1[3]);
        *(float4*)(ACT + (lane+32)*TB+4) = make_float4(qq1[4],qq1[5],qq1[6],qq1[7]);
        __syncwarp();
        {
            u64t pa[4] = {0ull,0ull,0ull,0ull};
#pragma unroll 2
            for (int j = 0; j < 16; j++) {
                float4 w = WT4[lane*WPAD4 + j];
#pragma unroll
                for (int e = 0; e < 4; e++) {
                    ulonglong2 aA = *(const ulonglong2*)(ACT + (4*j+e)*TB);
                    ulonglong2 aB = *(const ulonglong2*)(ACT + (4*j+e)*TB + 4);
                    acc4(dup2(((const float*)&w)[e]), aA, aB, pa);
                }
            }
            float pq[TB], qv[TB];
#pragma unroll
            for (int p = 0; p < 4; p++) up2(pa[p], pq[2*p], pq[2*p+1]);
#pragma unroll
            for (int t = 0; t < TB; t++) qv[t] = __expf(pq[t] - xdq[t]) * rsM;
            const long long tile_g = base >> 4;
            const int half = ((int)base >> 3) & 1;
            float* qb = d_qp + tile_g*512 + half*8 + lane*16;
            *(float4*)qb     = make_float4(qv[0],qv[1],qv[2],qv[3]);
            *(float4*)(qb+4) = make_float4(qv[4],qv[5],qv[6],qv[7]);
        }

        // ---- v ----
        float v0t[TB], v1t[TB];
#pragma unroll
        for (int p = 0; p < 4; p++) {
            up2(va[0][p], v0t[2*p], v0t[2*p+1]);
            up2(va[1][p], v1t[2*p], v1t[2*p+1]);
        }
#pragma unroll
        for (int t = 0; t < TB; t++) {
            d_v[(base + t)*64 + lane]      = v0t[t];
            d_v[(base + t)*64 + lane + 32] = v1t[t];
        }
        __syncwarp();
    }
}

// ===================== zero =====================
__global__ void kernelZero() {
    int i = blockIdx.x*blockDim.x + threadIdx.x;
    if (i < BATCH*MF)     d_kpsum[i] = 0.f;
    if (i < BATCH*DIM*MF) d_kptv[i]  = 0.f;
}

// ===================== Kernel B =====================
#define B_TILE 8
__global__ void __launch_bounds__(256) kernelB()
{
    __shared__ float sv [B_TILE*64];
    __shared__ float skp[B_TILE*32];
    const int tid = threadIdx.x;
    const int b   = blockIdx.y;
    const int m   = tid & 31, dg = tid >> 5;

    float acc[8];
#pragma unroll
    for (int j = 0; j < 8; j++) acc[j] = 0.f;
    float ks = 0.f;

    const int t0 = blockIdx.x * (TSEQ/8);
    const int t1 = t0 + (TSEQ/8);
    for (int base = t0; base < t1; base += B_TILE) {
        __syncthreads();
        {
            const float4* src = (const float4*)(d_v + ((long long)(b*TSEQ + base))*64);
            if (tid < B_TILE*16) ((float4*)sv)[tid] = src[tid];
            const float4* srck = (const float4*)(d_kp + ((long long)(b*TSEQ + base))*32);
            if (tid < B_TILE*8) ((float4*)skp)[tid] = srck[tid];
        }
        __syncthreads();
#pragma unroll
        for (int tt = 0; tt < B_TILE; tt++) {
            float kpm = skp[tt*32 + m];
#pragma unroll
            for (int j = 0; j < 8; j++)
                acc[j] = fmaf(kpm, sv[tt*64 + dg*8 + j], acc[j]);
            if (dg == 0) ks += kpm;
        }
    }
#pragma unroll
    for (int j = 0; j < 8; j++)
        atomicAdd(&d_kptv[b*2048 + (dg*8 + j)*32 + m], acc[j]);
    if (dg == 0) atomicAdd(&d_kpsum[b*32 + m], ks);
}

// ===================== Kernel C (8-col x 4-token register tiles) =====================
#define C_W2    0
#define C_WM1   4352
#define C_WM2   8704
#define C_KPTV  13056
#define C_KPS2  15232
#define C_B2    15296
#define C_G2    15364
#define C_BE2   15432
#define C_BM1   15500
#define C_BM2   15568
#define C_ACT   15636
#define C_QP    (C_ACT + NW*1024)
#define C_SMEM_BYTES ((C_QP + NW*512)*4)

__device__ __forceinline__ void gstep(const float* ap, const float* wp, u64t acc[8][2]) {
    ulonglong2 av = *(const ulonglong2*)ap;
    float4 w0 = *(const float4*)wp;
    float4 w1 = *(const float4*)(wp + 4);
#pragma unroll
    for (int f = 0; f < 4; f++) {
        u64t wd = dup2(((const float*)&w0)[f]);
        acc[f][0] = ffma2(wd, av.x, acc[f][0]);
        acc[f][1] = ffma2(wd, av.y, acc[f][1]);
    }
#pragma unroll
    for (int f = 0; f < 4; f++) {
        u64t wd = dup2(((const float*)&w1)[f]);
        acc[4+f][0] = ffma2(wd, av.x, acc[4+f][0]);
        acc[4+f][1] = ffma2(wd, av.y, acc[4+f][1]);
    }
}
// wbase must ALREADY include the lane's wc column offset.
__device__ __forceinline__ void gemm64(const float* ACTw, int r, const float* wbase, u64t acc[8][2]) {
#pragma unroll 2
    for (int kg = 0; kg < 8; kg++) {
        const float* ap = ACTw + kg*128 + 4*(r ^ (kg & 3));
        const float* wp = wbase + kg*8*CW;
#pragma unroll
        for (int kk = 0; kk < 8; kk++)
            gstep(ap + kk*16, wp + kk*CW, acc);
    }
}
__device__ __forceinline__ void sts8(float* ACTw, int c, int r, u64t v[8][2]) {
    int sw = 4*(r ^ (c & 3));
#pragma unroll
    for (int f = 0; f < 8; f++)
        *(ulonglong2*)(ACTw + (8*c+f)*16 + sw) = make_ulonglong2(v[f][0], v[f][1]);
}
__device__ __forceinline__ void bias8(const float* base, int wc, u64t a[8][2]) {
    float4 b0 = *(const float4*)(base + wc), b1 = *(const float4*)(base + wc + 4);
#pragma unroll
    for (int f = 0; f < 4; f++) { u64t d = dup2(((const float*)&b0)[f]); a[f][0]=d; a[f][1]=d; }
#pragma unroll
    for (int f = 0; f < 4; f++) { u64t d = dup2(((const float*)&b1)[f]); a[4+f][0]=d; a[4+f][1]=d; }
}

__global__ void __launch_bounds__(512) kernelC(
    const float* __restrict__ W2,  const float* __restrict__ b2,
    const float* __restrict__ g2,  const float* __restrict__ be2,
    const float* __restrict__ Wm1, const float* __restrict__ bm1,
    const float* __restrict__ Wm2, const float* __restrict__ bm2,
    float* __restrict__ out)
{
    extern __shared__ float sm[];
    const int tid = threadIdx.x, lane = tid & 31, warp = tid >> 5;
    const int b = blockIdx.y;
    const int c = lane & 7, r = lane >> 3;
    const int wc = 8*c + 4*(c >> 2);
    const int tb4 = 4*r;

    for (int idx = tid; idx < 4096; idx += 512) {
        int k = idx >> 6, j = idx & 63;
        int pos = k*CW + j + 4*(j >> 5);
        sm[C_W2  + pos] = W2 [idx];
        sm[C_WM1 + pos] = Wm1[idx];
        sm[C_WM2 + pos] = Wm2[idx];
    }
    for (int idx = tid; idx < 2048; idx += 512) {
        int d = idx >> 5, m = idx & 31;
        sm[C_KPTV + m*CW + d + 4*(d >> 5)] = d_kptv[b*2048 + idx];
    }
    if (tid < 32) {
        float v = d_kpsum[b*32 + tid];
        sm[C_KPS2 + 2*tid] = v; sm[C_KPS2 + 2*tid + 1] = v;
    }
    if (tid < 64) {
        int pos = tid + 4*(tid >> 5);
        sm[C_B2  + pos] = b2 [tid];
        sm[C_G2  + pos] = g2 [tid];
        sm[C_BE2 + pos] = be2[tid];
        sm[C_BM1 + pos] = bm1[tid];
        sm[C_BM2 + pos] = bm2[tid];
    }
    __syncthreads();

    float* ACTw = sm + C_ACT + warp*1024;
    float* QPw  = sm + C_QP  + warp*512;
    const float inv64 = 1.0f/64.0f;
    const long long btile = (long long)b*NTILE;

    for (int tile = blockIdx.x*NW + warp; tile < NTILE; tile += gridDim.x*NW) {
        {
            const float4* qs = (const float4*)(d_qp + (btile + tile)*512);
            float4* qd = (float4*)QPw;
            qd[lane] = qs[lane]; qd[lane+32] = qs[lane+32];
            qd[lane+64] = qs[lane+64]; qd[lane+96] = qs[lane+96];
        }
        __syncwarp();

        // ---- S1: att = qp @ kptv^T ----
        u64t acc[8][2];
#pragma unroll
        for (int f = 0; f < 8; f++) { acc[f][0] = 0ull; acc[f][1] = 0ull; }
#pragma unroll 4
        for (int m = 0; m < 32; m++)
            gstep(QPw + m*16 + tb4, sm + C_KPTV + m*CW + wc, acc);
        u64t D0 = 0ull, D1 = 0ull;
#pragma unroll 8
        for (int m = 0; m < 32; m++) {
            ulonglong2 av = *(const ulonglong2*)(QPw + m*16 + tb4);
            u64t kd = *(const u64t*)(sm + C_KPS2 + 2*m);
            D0 = ffma2(av.x, kd, D0); D1 = ffma2(av.y, kd, D1);
        }
        float dd0, dd1, dd2, dd3;
        up2(D0, dd0, dd1); up2(D1, dd2, dd3);
        u64t rp0 = pack2(1.0f/(dd0+1e-8f), 1.0f/(dd1+1e-8f));
        u64t rp1 = pack2(1.0f/(dd2+1e-8f), 1.0f/(dd3+1e-8f));
#pragma unroll
        for (int f = 0; f < 8; f++) {
            acc[f][0] = mul2(acc[f][0], rp0);
            acc[f][1] = mul2(acc[f][1], rp1);
        }
        __syncwarp();
        sts8(ACTw, c, r, acc);
        __syncwarp();

        // ---- S2: y = att @ W2 + b2 + v ----
        u64t yy[8][2];
        bias8(sm + C_B2, wc, yy);
        gemm64(ACTw, r, sm + C_W2 + wc, yy);
        {
            const long long tokg = (long long)b*TSEQ + tile*16 + tb4;
            const float* vb = d_v + tokg*64 + 8*c;
#pragma unroll
            for (int p = 0; p < 2; p++) {
                float4 a0 = *(const float4*)(vb + (2*p)*64);
                float4 a1 = *(const float4*)(vb + (2*p)*64 + 4);
                float4 c0 = *(const float4*)(vb + (2*p+1)*64);
                float4 c1 = *(const float4*)(vb + (2*p+1)*64 + 4);
#pragma unroll
                for (int f = 0; f < 4; f++) {
                    yy[f][p]   = add2(yy[f][p],   pack2(((const float*)&a0)[f], ((const float*)&c0)[f]));
                    yy[4+f][p] = add2(yy[4+f][p], pack2(((const float*)&a1)[f], ((const float*)&c1)[f]));
                }
            }
        }

        // ---- LN2 ----
        u64t mu[2], iv[2];
        {
            u64t sp0 = yy[0][0], sp1 = yy[0][1];
#pragma unroll
            for (int f = 1; f < 8; f++) { sp0 = add2(sp0, yy[f][0]); sp1 = add2(sp1, yy[f][1]); }
#pragma unroll
            for (int msk = 1; msk < 8; msk <<= 1) {
                sp0 = add2(sp0, shflx(sp0, msk));
                sp1 = add2(sp1, shflx(sp1, msk));
            }
            u64t i64 = dup2(inv64);
            mu[0] = mul2(sp0, i64); mu[1] = mul2(sp1, i64);
            u64t mn0 = mul2(mu[0], dup2(-1.f)), mn1 = mul2(mu[1], dup2(-1.f));
            u64t vs0 = 0ull, vs1 = 0ull;
#pragma unroll
            for (int f = 0; f < 8; f++) {
                u64t e0 = add2(yy[f][0], mn0), e1 = add2(yy[f][1], mn1);
                vs0 = ffma2(e0, e0, vs0); vs1 = ffma2(e1, e1, vs1);
            }
#pragma unroll
            for (int msk = 1; msk < 8; msk <<= 1) {
                vs0 = add2(vs0, shflx(vs0, msk));
                vs1 = add2(vs1, shflx(vs1, msk));
            }
            float v0, v1, v2, v3;
            up2(vs0, v0, v1); up2(vs1, v2, v3);
            iv[0] = pack2(rsqrtf(v0*inv64 + 1e-5f), rsqrtf(v1*inv64 + 1e-5f));
            iv[1] = pack2(rsqrtf(v2*inv64 + 1e-5f), rsqrtf(v3*inv64 + 1e-5f));
        }
        {
            u64t gd[8][2], yn[8][2];
            bias8(sm + C_G2, wc, gd);
            u64t mn0 = mul2(mu[0], dup2(-1.f)), mn1 = mul2(mu[1], dup2(-1.f));
#pragma unroll
            for (int f = 0; f < 8; f++) {
                yn[f][0] = mul2(mul2(add2(yy[f][0], mn0), iv[0]), gd[f][0]);
                yn[f][1] = mul2(mul2(add2(yy[f][1], mn1), iv[1]), gd[f][1]);
            }
            bias8(sm + C_BE2, wc, gd);
#pragma unroll
            for (int f = 0; f < 8; f++) {
                yn[f][0] = add2(yn[f][0], gd[f][0]);
                yn[f][1] = add2(yn[f][1], gd[f][1]);
            }
            __syncwarp();
            sts8(ACTw, c, r, yn);
            __syncwarp();
        }

        // ---- S3: m1 + GELU ----
        {
            u64t za[8][2];
            bias8(sm + C_BM1, wc, za);
            gemm64(ACTw, r, sm + C_WM1 + wc, za);
#pragma unroll
            for (int f = 0; f < 8; f++) {
#pragma unroll
                for (int p = 0; p < 2; p++) {
                    float u, v; up2(za[f][p], u, v);
                    za[f][p] = pack2(gelu(u), gelu(v));
                }
            }
            __syncwarp();
            sts8(ACTw, c, r, za);
            __syncwarp();
        }

        // ---- S4: m2 + residual -> out ----
        {
            u64t oa[8][2];
            bias8(sm + C_BM2, wc, oa);
            gemm64(ACTw, r, sm + C_WM2 + wc, oa);
#pragma unroll
            for (int f = 0; f < 8; f++) {
                oa[f][0] = add2(oa[f][0], yy[f][0]);
                oa[f][1] = add2(oa[f][1], yy[f][1]);
            }
            const long long tokg = (long long)b*TSEQ + tile*16 + tb4;
            float* ob = out + tokg*64 + 8*c;
#pragma unroll
            for (int p = 0; p < 2; p++) {
                float lo[8], hi[8];
#pragma unroll
                for (int f = 0; f < 8; f++) up2(oa[f][p], lo[f], hi[f]);
                *(float4*)(ob + (2*p)*64)       = make_float4(lo[0],lo[1],lo[2],lo[3]);
                *(float4*)(ob + (2*p)*64 + 4)   = make_float4(lo[4],lo[5],lo[6],lo[7]);
                *(float4*)(ob + (2*p+1)*64)     = make_float4(hi[0],hi[1],hi[2],hi[3]);
                *(float4*)(ob + (2*p+1)*64 + 4) = make_float4(hi[4],hi[5],hi[6],hi[7]);
            }
        }
        __syncwarp();
    }
}

// ===================== launch =====================
extern "C" void kernel_launch(void* const* d_in, const int* in_sizes, int n_in,
                              void* d_out, int out_size)
{
    const float* x   = (const float*)d_in[0];
    const float* W1  = (const float*)d_in[1];
    const float* b1  = (const float*)d_in[2];
    const float* Wk  = (const float*)d_in[3];
    const float* bk  = (const float*)d_in[4];
    const float* W2  = (const float*)d_in[5];
    const float* b2  = (const float*)d_in[6];
    const float* g1  = (const float*)d_in[7];
    const float* be1 = (const float*)d_in[8];
    const float* g2  = (const float*)d_in[9];
    const float* be2 = (const float*)d_in[10];
    const float* Wm1 = (const float*)d_in[11];
    const float* bm1 = (const float*)d_in[12];
    const float* Wm2 = (const float*)d_in[13];
    const float* bm2 = (const float*)d_in[14];
    const float* wrf = (const float*)d_in[15];
    float* out = (float*)d_out;

    cudaFuncSetAttribute(kernelA, cudaFuncAttributeMaxDynamicSharedMemorySize, A_SMEM_BYTES);
    cudaFuncSetAttribute(kernelC, cudaFuncAttributeMaxDynamicSharedMemorySize, C_SMEM_BYTES);

    kernelA<<<148, 512, A_SMEM_BYTES>>>(x, W1, b1, Wk, bk, g1, be1, wrf);
    kernelZero<<<(BATCH*DIM*MF + 255)/256, 256>>>();
    kernelB<<<dim3(8, BATCH), 256>>>();
    kernelC<<<dim3(7, BATCH), 512, C_SMEM_BYTES>>>(W2, b2, g2, be2, Wm1, bm1, Wm2, bm2, out);
}